// round 2
// baseline (speedup 1.0000x reference)
#include <cuda_runtime.h>
#include <cuda_bf16.h>
#include <math.h>

// Problem constants
#define Bsz 2
#define Sq  2048
#define Dm  2048
#define Hh  32
#define KVH 8
#define Gg  4          // H / KVH
#define DH  64
#define ROWS (Bsz*Sq)  // 4096
#define QC  (Hh*DH)    // 2048
#define KC  (KVH*DH)   // 512

// Scratch buffers (static device allocations are allowed)
__device__ float g_Q[(size_t)ROWS * QC];
__device__ float g_K[(size_t)ROWS * KC];
__device__ float g_V[(size_t)ROWS * KC];
__device__ float g_O[(size_t)ROWS * QC];

// ---------------------------------------------------------------------------
// Tiled SGEMM: C[M,N] = A[M,K] * B[N,K]^T   (row-major, M,N multiples of 64,
// K multiple of 16). 64x64 tile, BK=16, 256 threads, 4x4 per thread.
// ---------------------------------------------------------------------------
__global__ __launch_bounds__(256) void sgemm_abt(
    const float* __restrict__ A, const float* __restrict__ B,
    float* __restrict__ C, int M, int N, int K)
{
    __shared__ float As[16][68];
    __shared__ float Bs[16][68];

    const int tx = threadIdx.x;          // 0..15
    const int ty = threadIdx.y;          // 0..15
    const int tid = ty * 16 + tx;
    const int row0 = blockIdx.y * 64;
    const int col0 = blockIdx.x * 64;

    const int lm = tid >> 2;             // 0..63
    const int lk = (tid & 3) * 4;        // 0,4,8,12

    const float* Ag = A + (size_t)(row0 + lm) * K + lk;
    const float* Bg = B + (size_t)(col0 + lm) * K + lk;

    float acc[4][4];
#pragma unroll
    for (int i = 0; i < 4; i++)
#pragma unroll
        for (int j = 0; j < 4; j++) acc[i][j] = 0.f;

    for (int k0 = 0; k0 < K; k0 += 16) {
        float4 a  = *(const float4*)(Ag + k0);
        float4 bv = *(const float4*)(Bg + k0);
        As[lk + 0][lm] = a.x;  As[lk + 1][lm] = a.y;
        As[lk + 2][lm] = a.z;  As[lk + 3][lm] = a.w;
        Bs[lk + 0][lm] = bv.x; Bs[lk + 1][lm] = bv.y;
        Bs[lk + 2][lm] = bv.z; Bs[lk + 3][lm] = bv.w;
        __syncthreads();

#pragma unroll
        for (int kk = 0; kk < 16; kk++) {
            float4 av = *(const float4*)&As[kk][ty * 4];
            float4 bb = *(const float4*)&Bs[kk][tx * 4];
            acc[0][0] += av.x * bb.x; acc[0][1] += av.x * bb.y;
            acc[0][2] += av.x * bb.z; acc[0][3] += av.x * bb.w;
            acc[1][0] += av.y * bb.x; acc[1][1] += av.y * bb.y;
            acc[1][2] += av.y * bb.z; acc[1][3] += av.y * bb.w;
            acc[2][0] += av.z * bb.x; acc[2][1] += av.z * bb.y;
            acc[2][2] += av.z * bb.z; acc[2][3] += av.z * bb.w;
            acc[3][0] += av.w * bb.x; acc[3][1] += av.w * bb.y;
            acc[3][2] += av.w * bb.z; acc[3][3] += av.w * bb.w;
        }
        __syncthreads();
    }

#pragma unroll
    for (int i = 0; i < 4; i++) {
        float4 o;
        o.x = acc[i][0]; o.y = acc[i][1]; o.z = acc[i][2]; o.w = acc[i][3];
        *(float4*)&C[(size_t)(row0 + ty * 4 + i) * N + col0 + tx * 4] = o;
    }
}

// ---------------------------------------------------------------------------
// In-place RoPE: X is (ROWS, C) with C = heads*64. cos/sin are (ROWS, 64).
// Each thread handles one (row, head, d<32) pair.
// ---------------------------------------------------------------------------
__global__ void rope_kernel(float* __restrict__ X,
                            const float* __restrict__ cosb,
                            const float* __restrict__ sinb,
                            int C, int total_pairs)
{
    int idx = blockIdx.x * blockDim.x + threadIdx.x;
    if (idx >= total_pairs) return;
    int per_row = C >> 1;
    int row  = idx / per_row;
    int p    = idx - row * per_row;
    int head = p >> 5;
    int d    = p & 31;
    int col1 = head * 64 + d;
    int col2 = col1 + 32;

    float c1 = cosb[row * 64 + d];
    float s1 = sinb[row * 64 + d];
    float c2 = cosb[row * 64 + d + 32];
    float s2 = sinb[row * 64 + d + 32];

    size_t base = (size_t)row * C;
    float x1 = X[base + col1];
    float x2 = X[base + col2];
    X[base + col1] = x1 * c1 - x2 * s1;   // rotate_half first half: -x2
    X[base + col2] = x2 * c2 + x1 * s2;   // rotate_half second half: +x1
}

// ---------------------------------------------------------------------------
// Flash attention (causal, GQA). Block = (qtile, h, b), 256 threads.
// 64 q-rows per block, 4 threads per row, each thread owns 16 output dims.
// ---------------------------------------------------------------------------
#define TSTRIDE 65

__global__ __launch_bounds__(256) void flash_kernel(
    const float* __restrict__ Q, const float* __restrict__ K,
    const float* __restrict__ V, float* __restrict__ O)
{
    const int qt = blockIdx.x;
    const int h  = blockIdx.y;
    const int b  = blockIdx.z;
    const int kvh = h >> 2;           // h / G

    extern __shared__ float sm[];
    float* Qs = sm;                    // [64][65]
    float* Ks = sm + 64 * TSTRIDE;
    float* Vs = sm + 2 * 64 * TSTRIDE;
    float* Ps = sm + 3 * 64 * TSTRIDE;

    const int tid  = threadIdx.x;
    const int row  = tid >> 2;
    const int quad = tid & 3;
    const int q0   = qt * 64;
    const int qi   = q0 + row;

    // Load Q tile
    for (int idx = tid; idx < 64 * 64; idx += 256) {
        int i = idx >> 6, d = idx & 63;
        Qs[i * TSTRIDE + d] = Q[(size_t)(b * Sq + q0 + i) * QC + h * DH + d];
    }

    float m = -1e30f, l = 0.f;
    float acc[16];
#pragma unroll
    for (int i = 0; i < 16; i++) acc[i] = 0.f;

    for (int kt = 0; kt <= qt; ++kt) {
        const int k0 = kt * 64;
        __syncthreads();   // prior-iter Vs/Ps reads done (also covers Qs first iter)
        for (int idx = tid; idx < 64 * 64; idx += 256) {
            int j = idx >> 6, d = idx & 63;
            size_t g = (size_t)(b * Sq + k0 + j) * KC + kvh * DH + d;
            Ks[j * TSTRIDE + d] = K[g];
            Vs[j * TSTRIDE + d] = V[g];
        }
        __syncthreads();

        // scores: 16 k-columns per thread
        float s[16];
#pragma unroll
        for (int jj = 0; jj < 16; jj++) s[jj] = 0.f;
#pragma unroll 8
        for (int d = 0; d < 64; d++) {
            float qd = Qs[row * TSTRIDE + d];
#pragma unroll
            for (int jj = 0; jj < 16; jj++)
                s[jj] += qd * Ks[(quad * 16 + jj) * TSTRIDE + d];
        }

        // scale + causal mask + tile max
        float tmax = -1e30f;
#pragma unroll
        for (int jj = 0; jj < 16; jj++) {
            int kj = k0 + quad * 16 + jj;
            s[jj] = (kj <= qi) ? s[jj] * 0.125f : -1e30f;
            tmax = fmaxf(tmax, s[jj]);
        }
        tmax = fmaxf(tmax, __shfl_xor_sync(0xffffffffu, tmax, 1));
        tmax = fmaxf(tmax, __shfl_xor_sync(0xffffffffu, tmax, 2));

        float mn   = fmaxf(m, tmax);
        float corr = __expf(m - mn);
        float ls   = 0.f;
#pragma unroll
        for (int jj = 0; jj < 16; jj++) {
            float p = __expf(s[jj] - mn);
            Ps[row * TSTRIDE + quad * 16 + jj] = p;
            ls += p;
        }
        ls += __shfl_xor_sync(0xffffffffu, ls, 1);
        ls += __shfl_xor_sync(0xffffffffu, ls, 2);
        l = l * corr + ls;
        m = mn;
#pragma unroll
        for (int dd = 0; dd < 16; dd++) acc[dd] *= corr;

        __syncwarp();   // Ps row written by this warp's quad mates

#pragma unroll 8
        for (int j = 0; j < 64; j++) {
            float p = Ps[row * TSTRIDE + j];
#pragma unroll
            for (int dd = 0; dd < 16; dd++)
                acc[dd] += p * Vs[j * TSTRIDE + quad * 16 + dd];
        }
    }

    float inv = 1.f / l;
#pragma unroll
    for (int dd = 0; dd < 16; dd++)
        O[(size_t)(b * Sq + qi) * QC + h * DH + quad * 16 + dd] = acc[dd] * inv;
}

// ---------------------------------------------------------------------------
// kernel_launch
// Inputs: 0 hidden_states (B,S,D) f32, 1 cos (B,S,DH), 2 sin (B,S,DH),
//         3 attention_mask (ignored; exactly causal), 4 Wq (2048,2048),
//         5 Wk (512,2048), 6 Wv (512,2048), 7 Wo (2048,2048)
// Output: (B,S,D) f32
// ---------------------------------------------------------------------------
extern "C" void kernel_launch(void* const* d_in, const int* in_sizes, int n_in,
                              void* d_out, int out_size)
{
    const float* hidden = (const float*)d_in[0];
    const float* cosb   = (const float*)d_in[1];
    const float* sinb   = (const float*)d_in[2];
    const float* Wq     = (const float*)d_in[4];
    const float* Wk     = (const float*)d_in[5];
    const float* Wv     = (const float*)d_in[6];
    const float* Wo     = (const float*)d_in[7];
    float* out = (float*)d_out;

    float *Qb, *Kb, *Vb, *Ob;
    cudaGetSymbolAddress((void**)&Qb, g_Q);
    cudaGetSymbolAddress((void**)&Kb, g_K);
    cudaGetSymbolAddress((void**)&Vb, g_V);
    cudaGetSymbolAddress((void**)&Ob, g_O);

    dim3 tb(16, 16);

    // QKV projections
    sgemm_abt<<<dim3(QC / 64, ROWS / 64), tb>>>(hidden, Wq, Qb, ROWS, QC, Dm);
    sgemm_abt<<<dim3(KC / 64, ROWS / 64), tb>>>(hidden, Wk, Kb, ROWS, KC, Dm);
    sgemm_abt<<<dim3(KC / 64, ROWS / 64), tb>>>(hidden, Wv, Vb, ROWS, KC, Dm);

    // RoPE on Q and K
    {
        int pq = ROWS * (QC / 2);
        rope_kernel<<<(pq + 255) / 256, 256>>>(Qb, cosb, sinb, QC, pq);
        int pk = ROWS * (KC / 2);
        rope_kernel<<<(pk + 255) / 256, 256>>>(Kb, cosb, sinb, KC, pk);
    }

    // Flash attention
    {
        static int smem_set = 0;
        int smem_bytes = 4 * 64 * TSTRIDE * (int)sizeof(float);  // 66560
        if (!smem_set) {
            cudaFuncSetAttribute(flash_kernel,
                cudaFuncAttributeMaxDynamicSharedMemorySize, smem_bytes);
            smem_set = 1;
        }
        dim3 grid(Sq / 64, Hh, Bsz);
        flash_kernel<<<grid, 256, smem_bytes>>>(Qb, Kb, Vb, Ob);
    }

    // Output projection
    sgemm_abt<<<dim3(Dm / 64, ROWS / 64), tb>>>(Ob, Wo, out, ROWS, Dm, Dm);
}

// round 3
// speedup vs baseline: 3.2773x; 3.2773x over previous
#include <cuda_runtime.h>
#include <cuda_bf16.h>
#include <math.h>

// Problem constants
#define Bsz 2
#define Sq  2048
#define Dm  2048
#define Hh  32
#define KVH 8
#define DH  64
#define ROWS (Bsz*Sq)  // 4096
#define QC  (Hh*DH)    // 2048
#define KC  (KVH*DH)   // 512

// Scratch buffers
__device__ float g_Q[(size_t)ROWS * QC];
__device__ float g_K[(size_t)ROWS * KC];
__device__ float g_V[(size_t)ROWS * KC];
__device__ float g_O[(size_t)ROWS * QC];

__device__ __forceinline__ unsigned f2tf32(float x) {
    unsigned r;
    asm("cvt.rna.tf32.f32 %0, %1;" : "=r"(r) : "f"(x));
    return r;
}

// ---------------------------------------------------------------------------
// tf32 tensor-core GEMM: C[M,N] = A[M,K] * B[N,K]^T  (row-major, K-contig).
// 128x128 block tile, BK=16, 256 threads = 8 warps (2m x 4n),
// warp tile 64x32 via mma.sync.m16n8k8 (4 mtiles x 4 ntiles).
// M,N multiples of 128; K multiple of 16.
// ---------------------------------------------------------------------------
#define SSTR 20   // smem row stride (floats) — conflict-free for frag loads

__global__ __launch_bounds__(256) void gemm_tf32(
    const float* __restrict__ A, const float* __restrict__ B,
    float* __restrict__ C, int M, int N, int K)
{
    __shared__ unsigned As[128 * SSTR];
    __shared__ unsigned Bs[128 * SSTR];

    const int tid  = threadIdx.x;
    const int wid  = tid >> 5;
    const int lane = tid & 31;
    const int g    = lane >> 2;   // group id 0..7
    const int t    = lane & 3;    // thread-in-group 0..3
    const int wm   = wid & 1;     // 0..1
    const int wn   = wid >> 1;    // 0..3
    const int row0 = blockIdx.y * 128;
    const int col0 = blockIdx.x * 128;

    float c[4][4][4];
#pragma unroll
    for (int mt = 0; mt < 4; mt++)
#pragma unroll
        for (int nt = 0; nt < 4; nt++)
#pragma unroll
            for (int i = 0; i < 4; i++) c[mt][nt][i] = 0.f;

    for (int kc = 0; kc < K; kc += 16) {
#pragma unroll
        for (int it = 0; it < 2; it++) {
            int idx = tid + it * 256;       // 0..511
            int r   = idx >> 2;             // 0..127
            int kp  = (idx & 3) * 4;        // 0,4,8,12
            float4 av = *(const float4*)&A[(size_t)(row0 + r) * K + kc + kp];
            float4 bv = *(const float4*)&B[(size_t)(col0 + r) * K + kc + kp];
            uint4 at = make_uint4(f2tf32(av.x), f2tf32(av.y), f2tf32(av.z), f2tf32(av.w));
            uint4 bt = make_uint4(f2tf32(bv.x), f2tf32(bv.y), f2tf32(bv.z), f2tf32(bv.w));
            *(uint4*)&As[r * SSTR + kp] = at;
            *(uint4*)&Bs[r * SSTR + kp] = bt;
        }
        __syncthreads();

#pragma unroll
        for (int ks = 0; ks < 16; ks += 8) {
            unsigned a[4][4], bf[4][2];
#pragma unroll
            for (int mt = 0; mt < 4; mt++) {
                int rb = wm * 64 + mt * 16;
                a[mt][0] = As[(rb + g    ) * SSTR + ks + t    ];
                a[mt][1] = As[(rb + g + 8) * SSTR + ks + t    ];
                a[mt][2] = As[(rb + g    ) * SSTR + ks + t + 4];
                a[mt][3] = As[(rb + g + 8) * SSTR + ks + t + 4];
            }
#pragma unroll
            for (int nt = 0; nt < 4; nt++) {
                int cb = wn * 32 + nt * 8;
                bf[nt][0] = Bs[(cb + g) * SSTR + ks + t    ];
                bf[nt][1] = Bs[(cb + g) * SSTR + ks + t + 4];
            }
#pragma unroll
            for (int mt = 0; mt < 4; mt++)
#pragma unroll
                for (int nt = 0; nt < 4; nt++) {
                    asm volatile(
                        "mma.sync.aligned.m16n8k8.row.col.f32.tf32.tf32.f32 "
                        "{%0,%1,%2,%3}, {%4,%5,%6,%7}, {%8,%9}, {%0,%1,%2,%3};\n"
                        : "+f"(c[mt][nt][0]), "+f"(c[mt][nt][1]),
                          "+f"(c[mt][nt][2]), "+f"(c[mt][nt][3])
                        : "r"(a[mt][0]), "r"(a[mt][1]), "r"(a[mt][2]), "r"(a[mt][3]),
                          "r"(bf[nt][0]), "r"(bf[nt][1]));
                }
        }
        __syncthreads();
    }

    // Epilogue: c0/c1 -> row g cols 2t,2t+1 ; c2/c3 -> row g+8
#pragma unroll
    for (int mt = 0; mt < 4; mt++) {
#pragma unroll
        for (int nt = 0; nt < 4; nt++) {
            int r  = row0 + wm * 64 + mt * 16 + g;
            int cc = col0 + wn * 32 + nt * 8 + 2 * t;
            float2 lo = make_float2(c[mt][nt][0], c[mt][nt][1]);
            float2 hi = make_float2(c[mt][nt][2], c[mt][nt][3]);
            *(float2*)&C[(size_t)r * N + cc]       = lo;
            *(float2*)&C[(size_t)(r + 8) * N + cc] = hi;
        }
    }
}

// ---------------------------------------------------------------------------
// In-place RoPE (unchanged)
// ---------------------------------------------------------------------------
__global__ void rope_kernel(float* __restrict__ X,
                            const float* __restrict__ cosb,
                            const float* __restrict__ sinb,
                            int C, int total_pairs)
{
    int idx = blockIdx.x * blockDim.x + threadIdx.x;
    if (idx >= total_pairs) return;
    int per_row = C >> 1;
    int row  = idx / per_row;
    int p    = idx - row * per_row;
    int head = p >> 5;
    int d    = p & 31;
    int col1 = head * 64 + d;
    int col2 = col1 + 32;

    float c1 = cosb[row * 64 + d];
    float s1 = sinb[row * 64 + d];
    float c2 = cosb[row * 64 + d + 32];
    float s2 = sinb[row * 64 + d + 32];

    size_t base = (size_t)row * C;
    float x1 = X[base + col1];
    float x2 = X[base + col2];
    X[base + col1] = x1 * c1 - x2 * s1;
    X[base + col2] = x2 * c2 + x1 * s2;
}

// ---------------------------------------------------------------------------
// Flash attention v2: 4x4 register tiling, transposed Q/K smem, vectorized
// outer-product loops. Block = (qtile, h, b), 256 threads = 16x16 grid.
// Thread (tx,ty) owns q rows ty*4..+3 and (k cols | out dims) tx*4..+3.
// ---------------------------------------------------------------------------
#define FT 68   // smem row stride in floats (68*4=272 bytes, 16B aligned)

__global__ __launch_bounds__(256) void flash2_kernel(
    const float* __restrict__ Q, const float* __restrict__ K,
    const float* __restrict__ V, float* __restrict__ O)
{
    const int qt  = blockIdx.x;
    const int h   = blockIdx.y;
    const int b   = blockIdx.z;
    const int kvh = h >> 2;

    extern __shared__ float sm[];
    float* Qt = sm;                 // [64][FT]  Qt[d][q]
    float* Kt = sm + 64 * FT;       // Kt[d][j]
    float* Vs = sm + 2 * 64 * FT;   // Vs[j][d]
    float* Pt = sm + 3 * 64 * FT;   // Pt[j][q]

    const int tid = threadIdx.x;
    const int tx  = tid & 15;
    const int ty  = tid >> 4;
    const int q0  = qt * 64;

    // Load Q tile transposed: Qt[d][q]
    {
        int qrow = tid >> 2;
        int d0   = (tid & 3) * 16;
        const float* qg = &Q[(size_t)(b * Sq + q0 + qrow) * QC + h * DH + d0];
#pragma unroll
        for (int rep = 0; rep < 4; rep++) {
            float4 qv = *(const float4*)(qg + rep * 4);
            Qt[(d0 + rep * 4 + 0) * FT + qrow] = qv.x;
            Qt[(d0 + rep * 4 + 1) * FT + qrow] = qv.y;
            Qt[(d0 + rep * 4 + 2) * FT + qrow] = qv.z;
            Qt[(d0 + rep * 4 + 3) * FT + qrow] = qv.w;
        }
    }

    float m[4], l[4], acc[4][4];
#pragma unroll
    for (int i = 0; i < 4; i++) { m[i] = -1e30f; l[i] = 0.f; }
#pragma unroll
    for (int i = 0; i < 4; i++)
#pragma unroll
        for (int j = 0; j < 4; j++) acc[i][j] = 0.f;

    for (int kt = 0; kt <= qt; ++kt) {
        const int k0 = kt * 64;
        __syncthreads();   // prior-iter reads of Kt/Vs/Pt done (also covers Qt 1st iter)

        // Load K transposed (Kt[d][j]) and V natural (Vs[j][d])
        {
            int j  = tid >> 2;
            int d0 = (tid & 3) * 16;
            const float* kg = &K[(size_t)(b * Sq + k0 + j) * KC + kvh * DH + d0];
            const float* vg = &V[(size_t)(b * Sq + k0 + j) * KC + kvh * DH + d0];
#pragma unroll
            for (int rep = 0; rep < 4; rep++) {
                float4 kv = *(const float4*)(kg + rep * 4);
                Kt[(d0 + rep * 4 + 0) * FT + j] = kv.x;
                Kt[(d0 + rep * 4 + 1) * FT + j] = kv.y;
                Kt[(d0 + rep * 4 + 2) * FT + j] = kv.z;
                Kt[(d0 + rep * 4 + 3) * FT + j] = kv.w;
                *(float4*)&Vs[j * FT + d0 + rep * 4] = *(const float4*)(vg + rep * 4);
            }
        }
        __syncthreads();

        // S = Q K^T : outer product over d, 4x4 per thread
        float s[4][4];
#pragma unroll
        for (int i = 0; i < 4; i++)
#pragma unroll
            for (int j = 0; j < 4; j++) s[i][j] = 0.f;

#pragma unroll 4
        for (int d = 0; d < 64; d++) {
            float4 qv = *(float4*)&Qt[d * FT + ty * 4];
            float4 kv = *(float4*)&Kt[d * FT + tx * 4];
            s[0][0] += qv.x * kv.x; s[0][1] += qv.x * kv.y; s[0][2] += qv.x * kv.z; s[0][3] += qv.x * kv.w;
            s[1][0] += qv.y * kv.x; s[1][1] += qv.y * kv.y; s[1][2] += qv.y * kv.z; s[1][3] += qv.y * kv.w;
            s[2][0] += qv.z * kv.x; s[2][1] += qv.z * kv.y; s[2][2] += qv.z * kv.z; s[2][3] += qv.z * kv.w;
            s[3][0] += qv.w * kv.x; s[3][1] += qv.w * kv.y; s[3][2] += qv.w * kv.z; s[3][3] += qv.w * kv.w;
        }

        // scale + causal mask + per-row max (reduce across 16 tx lanes)
        float rmax[4];
#pragma unroll
        for (int i = 0; i < 4; i++) {
            int qi = q0 + ty * 4 + i;
            float mx = -1e30f;
#pragma unroll
            for (int j = 0; j < 4; j++) {
                int kj = k0 + tx * 4 + j;
                s[i][j] = (kj <= qi) ? s[i][j] * 0.125f : -1e30f;
                mx = fmaxf(mx, s[i][j]);
            }
            rmax[i] = mx;
        }
#pragma unroll
        for (int off = 1; off < 16; off <<= 1)
#pragma unroll
            for (int i = 0; i < 4; i++)
                rmax[i] = fmaxf(rmax[i], __shfl_xor_sync(0xffffffffu, rmax[i], off));

        float p[4][4], lsum[4];
#pragma unroll
        for (int i = 0; i < 4; i++) {
            float mn   = fmaxf(m[i], rmax[i]);
            float corr = __expf(m[i] - mn);
            float ls = 0.f;
#pragma unroll
            for (int j = 0; j < 4; j++) {
                p[i][j] = __expf(s[i][j] - mn);
                ls += p[i][j];
            }
            lsum[i] = ls;
            m[i] = mn;
            l[i] *= corr;
#pragma unroll
            for (int jj = 0; jj < 4; jj++) acc[i][jj] *= corr;
        }
#pragma unroll
        for (int off = 1; off < 16; off <<= 1)
#pragma unroll
            for (int i = 0; i < 4; i++)
                lsum[i] += __shfl_xor_sync(0xffffffffu, lsum[i], off);
#pragma unroll
        for (int i = 0; i < 4; i++) l[i] += lsum[i];

        // Store P transposed: Pt[j][q]
#pragma unroll
        for (int j = 0; j < 4; j++) {
            float4 pv = make_float4(p[0][j], p[1][j], p[2][j], p[3][j]);
            *(float4*)&Pt[(tx * 4 + j) * FT + ty * 4] = pv;
        }
        __syncthreads();

        // acc += P V : outer product over j
#pragma unroll 4
        for (int j = 0; j < 64; j++) {
            float4 pv = *(float4*)&Pt[j * FT + ty * 4];
            float4 vv = *(float4*)&Vs[j * FT + tx * 4];
            acc[0][0] += pv.x * vv.x; acc[0][1] += pv.x * vv.y; acc[0][2] += pv.x * vv.z; acc[0][3] += pv.x * vv.w;
            acc[1][0] += pv.y * vv.x; acc[1][1] += pv.y * vv.y; acc[1][2] += pv.y * vv.z; acc[1][3] += pv.y * vv.w;
            acc[2][0] += pv.z * vv.x; acc[2][1] += pv.z * vv.y; acc[2][2] += pv.z * vv.z; acc[2][3] += pv.z * vv.w;
            acc[3][0] += pv.w * vv.x; acc[3][1] += pv.w * vv.y; acc[3][2] += pv.w * vv.z; acc[3][3] += pv.w * vv.w;
        }
    }

    // Epilogue
#pragma unroll
    for (int i = 0; i < 4; i++) {
        float inv = 1.f / l[i];
        float4 o = make_float4(acc[i][0] * inv, acc[i][1] * inv,
                               acc[i][2] * inv, acc[i][3] * inv);
        *(float4*)&O[(size_t)(b * Sq + q0 + ty * 4 + i) * QC + h * DH + tx * 4] = o;
    }
}

// ---------------------------------------------------------------------------
// kernel_launch
// ---------------------------------------------------------------------------
extern "C" void kernel_launch(void* const* d_in, const int* in_sizes, int n_in,
                              void* d_out, int out_size)
{
    const float* hidden = (const float*)d_in[0];
    const float* cosb   = (const float*)d_in[1];
    const float* sinb   = (const float*)d_in[2];
    const float* Wq     = (const float*)d_in[4];
    const float* Wk     = (const float*)d_in[5];
    const float* Wv     = (const float*)d_in[6];
    const float* Wo     = (const float*)d_in[7];
    float* out = (float*)d_out;

    float *Qb, *Kb, *Vb, *Ob;
    cudaGetSymbolAddress((void**)&Qb, g_Q);
    cudaGetSymbolAddress((void**)&Kb, g_K);
    cudaGetSymbolAddress((void**)&Vb, g_V);
    cudaGetSymbolAddress((void**)&Ob, g_O);

    // QKV projections (tf32 tensor cores)
    gemm_tf32<<<dim3(QC / 128, ROWS / 128), 256>>>(hidden, Wq, Qb, ROWS, QC, Dm);
    gemm_tf32<<<dim3(KC / 128, ROWS / 128), 256>>>(hidden, Wk, Kb, ROWS, KC, Dm);
    gemm_tf32<<<dim3(KC / 128, ROWS / 128), 256>>>(hidden, Wv, Vb, ROWS, KC, Dm);

    // RoPE on Q and K
    {
        int pq = ROWS * (QC / 2);
        rope_kernel<<<(pq + 255) / 256, 256>>>(Qb, cosb, sinb, QC, pq);
        int pk = ROWS * (KC / 2);
        rope_kernel<<<(pk + 255) / 256, 256>>>(Kb, cosb, sinb, KC, pk);
    }

    // Flash attention
    {
        int smem_bytes = 4 * 64 * FT * (int)sizeof(float);  // 69632
        cudaFuncSetAttribute(flash2_kernel,
            cudaFuncAttributeMaxDynamicSharedMemorySize, smem_bytes);
        dim3 grid(Sq / 64, Hh, Bsz);
        flash2_kernel<<<grid, 256, smem_bytes>>>(Qb, Kb, Vb, Ob);
    }

    // Output projection
    gemm_tf32<<<dim3(Dm / 128, ROWS / 128), 256>>>(Ob, Wo, out, ROWS, Dm, Dm);
}

// round 4
// speedup vs baseline: 4.4441x; 1.3560x over previous
#include <cuda_runtime.h>
#include <cuda_bf16.h>
#include <math.h>

// Problem constants
#define Bsz 2
#define Sq  2048
#define Dm  2048
#define Hh  32
#define KVH 8
#define DH  64
#define ROWS (Bsz*Sq)  // 4096
#define QC  (Hh*DH)    // 2048
#define KC  (KVH*DH)   // 512

// Scratch buffers
__device__ float g_Q[(size_t)ROWS * QC];
__device__ float g_K[(size_t)ROWS * KC];
__device__ float g_V[(size_t)ROWS * KC];
__device__ float g_O[(size_t)ROWS * QC];

__device__ __forceinline__ unsigned f2tf32(float x) {
    unsigned r;
    asm("cvt.rna.tf32.f32 %0, %1;" : "=r"(r) : "f"(x));
    return r;
}

__device__ __forceinline__ void mma_tf32(float* c, const unsigned* a,
                                         unsigned b0, unsigned b1) {
    asm volatile(
        "mma.sync.aligned.m16n8k8.row.col.f32.tf32.tf32.f32 "
        "{%0,%1,%2,%3}, {%4,%5,%6,%7}, {%8,%9}, {%0,%1,%2,%3};\n"
        : "+f"(c[0]), "+f"(c[1]), "+f"(c[2]), "+f"(c[3])
        : "r"(a[0]), "r"(a[1]), "r"(a[2]), "r"(a[3]), "r"(b0), "r"(b1));
}

// ---------------------------------------------------------------------------
// tf32 tensor-core GEMM: C[M,N] = A[M,K] * B[N,K]^T (unchanged from round 3)
// ---------------------------------------------------------------------------
#define SSTR 20

__global__ __launch_bounds__(256) void gemm_tf32(
    const float* __restrict__ A, const float* __restrict__ B,
    float* __restrict__ C, int M, int N, int K)
{
    __shared__ unsigned As[128 * SSTR];
    __shared__ unsigned Bs[128 * SSTR];

    const int tid  = threadIdx.x;
    const int wid  = tid >> 5;
    const int lane = tid & 31;
    const int g    = lane >> 2;
    const int t    = lane & 3;
    const int wm   = wid & 1;
    const int wn   = wid >> 1;
    const int row0 = blockIdx.y * 128;
    const int col0 = blockIdx.x * 128;

    float c[4][4][4];
#pragma unroll
    for (int mt = 0; mt < 4; mt++)
#pragma unroll
        for (int nt = 0; nt < 4; nt++)
#pragma unroll
            for (int i = 0; i < 4; i++) c[mt][nt][i] = 0.f;

    for (int kc = 0; kc < K; kc += 16) {
#pragma unroll
        for (int it = 0; it < 2; it++) {
            int idx = tid + it * 256;
            int r   = idx >> 2;
            int kp  = (idx & 3) * 4;
            float4 av = *(const float4*)&A[(size_t)(row0 + r) * K + kc + kp];
            float4 bv = *(const float4*)&B[(size_t)(col0 + r) * K + kc + kp];
            uint4 at = make_uint4(f2tf32(av.x), f2tf32(av.y), f2tf32(av.z), f2tf32(av.w));
            uint4 bt = make_uint4(f2tf32(bv.x), f2tf32(bv.y), f2tf32(bv.z), f2tf32(bv.w));
            *(uint4*)&As[r * SSTR + kp] = at;
            *(uint4*)&Bs[r * SSTR + kp] = bt;
        }
        __syncthreads();

#pragma unroll
        for (int ks = 0; ks < 16; ks += 8) {
            unsigned a[4][4], bf[4][2];
#pragma unroll
            for (int mt = 0; mt < 4; mt++) {
                int rb = wm * 64 + mt * 16;
                a[mt][0] = As[(rb + g    ) * SSTR + ks + t    ];
                a[mt][1] = As[(rb + g + 8) * SSTR + ks + t    ];
                a[mt][2] = As[(rb + g    ) * SSTR + ks + t + 4];
                a[mt][3] = As[(rb + g + 8) * SSTR + ks + t + 4];
            }
#pragma unroll
            for (int nt = 0; nt < 4; nt++) {
                int cb = wn * 32 + nt * 8;
                bf[nt][0] = Bs[(cb + g) * SSTR + ks + t    ];
                bf[nt][1] = Bs[(cb + g) * SSTR + ks + t + 4];
            }
#pragma unroll
            for (int mt = 0; mt < 4; mt++)
#pragma unroll
                for (int nt = 0; nt < 4; nt++)
                    mma_tf32(c[mt][nt], a[mt], bf[nt][0], bf[nt][1]);
        }
        __syncthreads();
    }

#pragma unroll
    for (int mt = 0; mt < 4; mt++) {
#pragma unroll
        for (int nt = 0; nt < 4; nt++) {
            int r  = row0 + wm * 64 + mt * 16 + g;
            int cc = col0 + wn * 32 + nt * 8 + 2 * t;
            float2 lo = make_float2(c[mt][nt][0], c[mt][nt][1]);
            float2 hi = make_float2(c[mt][nt][2], c[mt][nt][3]);
            *(float2*)&C[(size_t)r * N + cc]       = lo;
            *(float2*)&C[(size_t)(r + 8) * N + cc] = hi;
        }
    }
}

// ---------------------------------------------------------------------------
// In-place RoPE (unchanged)
// ---------------------------------------------------------------------------
__global__ void rope_kernel(float* __restrict__ X,
                            const float* __restrict__ cosb,
                            const float* __restrict__ sinb,
                            int C, int total_pairs)
{
    int idx = blockIdx.x * blockDim.x + threadIdx.x;
    if (idx >= total_pairs) return;
    int per_row = C >> 1;
    int row  = idx / per_row;
    int p    = idx - row * per_row;
    int head = p >> 5;
    int d    = p & 31;
    int col1 = head * 64 + d;
    int col2 = col1 + 32;

    float c1 = cosb[row * 64 + d];
    float s1 = sinb[row * 64 + d];
    float c2 = cosb[row * 64 + d + 32];
    float s2 = sinb[row * 64 + d + 32];

    size_t base = (size_t)row * C;
    float x1 = X[base + col1];
    float x2 = X[base + col2];
    X[base + col1] = x1 * c1 - x2 * s1;
    X[base + col2] = x2 * c2 + x1 * s2;
}

// ---------------------------------------------------------------------------
// Flash attention v3: tf32 tensor cores for QK^T and PV.
// Block = (qtile, h, b), 128 threads = 4 warps. Warp w owns q-rows
// w*16..w*16+15 (two mma row-halves g, g+8). 64x64 K/V tiles.
// Smem layouts (stride FS=72, bank = 8t+g -> conflict-free frag loads):
//   Qt[d][q] (A frags), Kt[d][j] (B frags), Vs[j][d] (B frags), Pt[j][q] (A frags)
// ---------------------------------------------------------------------------
#define FS 72

__global__ __launch_bounds__(128) void flash3_kernel(
    const float* __restrict__ Q, const float* __restrict__ K,
    const float* __restrict__ V, float* __restrict__ O)
{
    const int qt  = blockIdx.x;
    const int h   = blockIdx.y;
    const int b   = blockIdx.z;
    const int kvh = h >> 2;

    extern __shared__ unsigned smu[];
    unsigned* Qt = smu;
    unsigned* Kt = smu + 64 * FS;
    unsigned* Vs = smu + 2 * 64 * FS;
    unsigned* Pt = smu + 3 * 64 * FS;

    const int tid  = threadIdx.x;
    const int w    = tid >> 5;
    const int lane = tid & 31;
    const int g    = lane >> 2;
    const int t    = lane & 3;
    const int q0   = qt * 64;

    // Load Q tile transposed as tf32: Qt[d][q]
    {
        int r  = tid >> 1;
        int d0 = (tid & 1) * 32;
        const float* qg = &Q[(size_t)(b * Sq + q0 + r) * QC + h * DH + d0];
#pragma unroll
        for (int i = 0; i < 8; i++) {
            float4 v = *(const float4*)(qg + i * 4);
            Qt[(d0 + i * 4 + 0) * FS + r] = f2tf32(v.x);
            Qt[(d0 + i * 4 + 1) * FS + r] = f2tf32(v.y);
            Qt[(d0 + i * 4 + 2) * FS + r] = f2tf32(v.z);
            Qt[(d0 + i * 4 + 3) * FS + r] = f2tf32(v.w);
        }
    }

    float m0 = -1e30f, m1 = -1e30f, l0 = 0.f, l1 = 0.f;
    float acc[8][4];
#pragma unroll
    for (int nt = 0; nt < 8; nt++)
#pragma unroll
        for (int i = 0; i < 4; i++) acc[nt][i] = 0.f;

    const int r0 = q0 + w * 16 + g;   // global q row (low half)
    const int r1 = r0 + 8;

    for (int kt = 0; kt <= qt; ++kt) {
        const int k0 = kt * 64;
        __syncthreads();   // all warps done with prev Kt/Vs (and Qt stores on iter 0)

        // Load K transposed (Kt[d][j]) and V natural (Vs[j][d]), tf32
        {
            int r  = tid >> 1;
            int d0 = (tid & 1) * 32;
            const float* kg = &K[(size_t)(b * Sq + k0 + r) * KC + kvh * DH + d0];
            const float* vg = &V[(size_t)(b * Sq + k0 + r) * KC + kvh * DH + d0];
#pragma unroll
            for (int i = 0; i < 8; i++) {
                float4 kv = *(const float4*)(kg + i * 4);
                Kt[(d0 + i * 4 + 0) * FS + r] = f2tf32(kv.x);
                Kt[(d0 + i * 4 + 1) * FS + r] = f2tf32(kv.y);
                Kt[(d0 + i * 4 + 2) * FS + r] = f2tf32(kv.z);
                Kt[(d0 + i * 4 + 3) * FS + r] = f2tf32(kv.w);
                float4 vv = *(const float4*)(vg + i * 4);
                uint4 vt  = make_uint4(f2tf32(vv.x), f2tf32(vv.y),
                                       f2tf32(vv.z), f2tf32(vv.w));
                *(uint4*)&Vs[r * FS + d0 + i * 4] = vt;
            }
        }
        __syncthreads();

        // ---- S = Q K^T (16x64 per warp) ----
        float sc[8][4];
#pragma unroll
        for (int nt = 0; nt < 8; nt++)
#pragma unroll
            for (int i = 0; i < 4; i++) sc[nt][i] = 0.f;

#pragma unroll
        for (int ks = 0; ks < 8; ks++) {
            unsigned a[4];
            a[0] = Qt[(ks * 8 + t    ) * FS + w * 16 + g    ];
            a[1] = Qt[(ks * 8 + t    ) * FS + w * 16 + g + 8];
            a[2] = Qt[(ks * 8 + t + 4) * FS + w * 16 + g    ];
            a[3] = Qt[(ks * 8 + t + 4) * FS + w * 16 + g + 8];
#pragma unroll
            for (int nt = 0; nt < 8; nt++) {
                unsigned b0 = Kt[(ks * 8 + t    ) * FS + nt * 8 + g];
                unsigned b1 = Kt[(ks * 8 + t + 4) * FS + nt * 8 + g];
                mma_tf32(sc[nt], a, b0, b1);
            }
        }

        // ---- softmax on C frags ----
        float rmax0 = -1e30f, rmax1 = -1e30f;
#pragma unroll
        for (int nt = 0; nt < 8; nt++) {
#pragma unroll
            for (int c2 = 0; c2 < 2; c2++) {
                float v0 = sc[nt][c2    ] * 0.125f;
                float v1 = sc[nt][c2 + 2] * 0.125f;
                if (kt == qt) {
                    int kj = k0 + nt * 8 + 2 * t + c2;
                    if (kj > r0) v0 = -1e30f;
                    if (kj > r1) v1 = -1e30f;
                }
                sc[nt][c2    ] = v0;
                sc[nt][c2 + 2] = v1;
                rmax0 = fmaxf(rmax0, v0);
                rmax1 = fmaxf(rmax1, v1);
            }
        }
        rmax0 = fmaxf(rmax0, __shfl_xor_sync(0xffffffffu, rmax0, 1));
        rmax0 = fmaxf(rmax0, __shfl_xor_sync(0xffffffffu, rmax0, 2));
        rmax1 = fmaxf(rmax1, __shfl_xor_sync(0xffffffffu, rmax1, 1));
        rmax1 = fmaxf(rmax1, __shfl_xor_sync(0xffffffffu, rmax1, 2));

        float mn0 = fmaxf(m0, rmax0), mn1 = fmaxf(m1, rmax1);
        float corr0 = __expf(m0 - mn0), corr1 = __expf(m1 - mn1);
        m0 = mn0; m1 = mn1;

        float ls0 = 0.f, ls1 = 0.f;
#pragma unroll
        for (int nt = 0; nt < 8; nt++) {
#pragma unroll
            for (int c2 = 0; c2 < 2; c2++) {
                float p0 = __expf(sc[nt][c2    ] - mn0);
                float p1 = __expf(sc[nt][c2 + 2] - mn1);
                ls0 += p0; ls1 += p1;
                Pt[(nt * 8 + 2 * t + c2) * FS + w * 16 + g    ] = f2tf32(p0);
                Pt[(nt * 8 + 2 * t + c2) * FS + w * 16 + g + 8] = f2tf32(p1);
            }
        }
        ls0 += __shfl_xor_sync(0xffffffffu, ls0, 1);
        ls0 += __shfl_xor_sync(0xffffffffu, ls0, 2);
        ls1 += __shfl_xor_sync(0xffffffffu, ls1, 1);
        ls1 += __shfl_xor_sync(0xffffffffu, ls1, 2);
        l0 = l0 * corr0 + ls0;
        l1 = l1 * corr1 + ls1;

#pragma unroll
        for (int nt = 0; nt < 8; nt++) {
            acc[nt][0] *= corr0; acc[nt][1] *= corr0;
            acc[nt][2] *= corr1; acc[nt][3] *= corr1;
        }

        __syncwarp();   // Pt columns are warp-local; order STS before LDS

        // ---- acc += P V (16x64 per warp) ----
#pragma unroll
        for (int ks = 0; ks < 8; ks++) {
            unsigned a[4];
            a[0] = Pt[(ks * 8 + t    ) * FS + w * 16 + g    ];
            a[1] = Pt[(ks * 8 + t    ) * FS + w * 16 + g + 8];
            a[2] = Pt[(ks * 8 + t + 4) * FS + w * 16 + g    ];
            a[3] = Pt[(ks * 8 + t + 4) * FS + w * 16 + g + 8];
#pragma unroll
            for (int nt = 0; nt < 8; nt++) {
                unsigned b0 = Vs[(ks * 8 + t    ) * FS + nt * 8 + g];
                unsigned b1 = Vs[(ks * 8 + t + 4) * FS + nt * 8 + g];
                mma_tf32(acc[nt], a, b0, b1);
            }
        }
    }

    // Epilogue
    float inv0 = 1.f / l0, inv1 = 1.f / l1;
    size_t orow0 = (size_t)(b * Sq + q0 + w * 16 + g) * QC;
    size_t orow1 = orow0 + 8 * (size_t)QC;
#pragma unroll
    for (int nt = 0; nt < 8; nt++) {
        int col = h * DH + nt * 8 + 2 * t;
        float2 lo = make_float2(acc[nt][0] * inv0, acc[nt][1] * inv0);
        float2 hi = make_float2(acc[nt][2] * inv1, acc[nt][3] * inv1);
        *(float2*)&O[orow0 + col] = lo;
        *(float2*)&O[orow1 + col] = hi;
    }
}

// ---------------------------------------------------------------------------
// kernel_launch
// ---------------------------------------------------------------------------
extern "C" void kernel_launch(void* const* d_in, const int* in_sizes, int n_in,
                              void* d_out, int out_size)
{
    const float* hidden = (const float*)d_in[0];
    const float* cosb   = (const float*)d_in[1];
    const float* sinb   = (const float*)d_in[2];
    const float* Wq     = (const float*)d_in[4];
    const float* Wk     = (const float*)d_in[5];
    const float* Wv     = (const float*)d_in[6];
    const float* Wo     = (const float*)d_in[7];
    float* out = (float*)d_out;

    float *Qb, *Kb, *Vb, *Ob;
    cudaGetSymbolAddress((void**)&Qb, g_Q);
    cudaGetSymbolAddress((void**)&Kb, g_K);
    cudaGetSymbolAddress((void**)&Vb, g_V);
    cudaGetSymbolAddress((void**)&Ob, g_O);

    // QKV projections (tf32 tensor cores)
    gemm_tf32<<<dim3(QC / 128, ROWS / 128), 256>>>(hidden, Wq, Qb, ROWS, QC, Dm);
    gemm_tf32<<<dim3(KC / 128, ROWS / 128), 256>>>(hidden, Wk, Kb, ROWS, KC, Dm);
    gemm_tf32<<<dim3(KC / 128, ROWS / 128), 256>>>(hidden, Wv, Vb, ROWS, KC, Dm);

    // RoPE on Q and K
    {
        int pq = ROWS * (QC / 2);
        rope_kernel<<<(pq + 255) / 256, 256>>>(Qb, cosb, sinb, QC, pq);
        int pk = ROWS * (KC / 2);
        rope_kernel<<<(pk + 255) / 256, 256>>>(Kb, cosb, sinb, KC, pk);
    }

    // Flash attention (tf32 tensor cores)
    {
        int smem_bytes = 4 * 64 * FS * (int)sizeof(unsigned);  // 73728
        cudaFuncSetAttribute(flash3_kernel,
            cudaFuncAttributeMaxDynamicSharedMemorySize, smem_bytes);
        dim3 grid(Sq / 64, Hh, Bsz);
        flash3_kernel<<<grid, 128, smem_bytes>>>(Qb, Kb, Vb, Ob);
    }

    // Output projection
    gemm_tf32<<<dim3(Dm / 128, ROWS / 128), 256>>>(Ob, Wo, out, ROWS, Dm, Dm);
}

// round 5
// speedup vs baseline: 5.8021x; 1.3056x over previous
#include <cuda_runtime.h>
#include <cuda_bf16.h>
#include <math.h>

// Problem constants
#define Bsz 2
#define Sq  2048
#define Dm  2048
#define Hh  32
#define KVH 8
#define DH  64
#define ROWS (Bsz*Sq)  // 4096
#define QC  (Hh*DH)    // 2048
#define KC  (KVH*DH)   // 512

// Scratch buffers
__device__ float g_Q[(size_t)ROWS * QC];
__device__ float g_K[(size_t)ROWS * KC];
__device__ float g_V[(size_t)ROWS * KC];
__device__ float g_O[(size_t)ROWS * QC];

__device__ __forceinline__ unsigned f2tf32(float x) {
    unsigned r;
    asm("cvt.rna.tf32.f32 %0, %1;" : "=r"(r) : "f"(x));
    return r;
}

__device__ __forceinline__ uint4 cvt4(float4 v) {
    return make_uint4(f2tf32(v.x), f2tf32(v.y), f2tf32(v.z), f2tf32(v.w));
}

__device__ __forceinline__ void mma_tf32(float* c, const unsigned* a,
                                         unsigned b0, unsigned b1) {
    asm volatile(
        "mma.sync.aligned.m16n8k8.row.col.f32.tf32.tf32.f32 "
        "{%0,%1,%2,%3}, {%4,%5,%6,%7}, {%8,%9}, {%0,%1,%2,%3};\n"
        : "+f"(c[0]), "+f"(c[1]), "+f"(c[2]), "+f"(c[3])
        : "r"(a[0]), "r"(a[1]), "r"(a[2]), "r"(a[3]), "r"(b0), "r"(b1));
}

// ---------------------------------------------------------------------------
// Double-buffered tf32 GEMM tile: C[.,N] tile (row0,col0) += A[M,K]*B[N,K]^T.
// 128x128 tile, BK=16, 256 threads, 2-stage smem + register prefetch,
// one __syncthreads per k-step.
// ---------------------------------------------------------------------------
#define SSTR 20

__device__ __forceinline__ void gemm_tile(
    const float* __restrict__ A, const float* __restrict__ B,
    float* __restrict__ C, int N, int K, int row0, int col0)
{
    __shared__ unsigned As[2][128 * SSTR];
    __shared__ unsigned Bs[2][128 * SSTR];

    const int tid  = threadIdx.x;
    const int wid  = tid >> 5;
    const int lane = tid & 31;
    const int g    = lane >> 2;
    const int t    = lane & 3;
    const int wm   = wid & 1;
    const int wn   = wid >> 1;

    int rr[2], kk[2];
    float4 pa[2], pb[2];
#pragma unroll
    for (int it = 0; it < 2; it++) {
        int idx = tid + it * 256;
        rr[it] = idx >> 2;
        kk[it] = (idx & 3) * 4;
        pa[it] = *(const float4*)&A[(size_t)(row0 + rr[it]) * K + kk[it]];
        pb[it] = *(const float4*)&B[(size_t)(col0 + rr[it]) * K + kk[it]];
    }

    float c[4][4][4];
#pragma unroll
    for (int mt = 0; mt < 4; mt++)
#pragma unroll
        for (int nt = 0; nt < 4; nt++)
#pragma unroll
            for (int i = 0; i < 4; i++) c[mt][nt][i] = 0.f;

    int s = 0;
    for (int kc = 0; kc < K; kc += 16) {
#pragma unroll
        for (int it = 0; it < 2; it++) {
            *(uint4*)&As[s][rr[it] * SSTR + kk[it]] = cvt4(pa[it]);
            *(uint4*)&Bs[s][rr[it] * SSTR + kk[it]] = cvt4(pb[it]);
        }
        __syncthreads();

        if (kc + 16 < K) {
#pragma unroll
            for (int it = 0; it < 2; it++) {
                pa[it] = *(const float4*)&A[(size_t)(row0 + rr[it]) * K + kc + 16 + kk[it]];
                pb[it] = *(const float4*)&B[(size_t)(col0 + rr[it]) * K + kc + 16 + kk[it]];
            }
        }

#pragma unroll
        for (int ks = 0; ks < 16; ks += 8) {
            unsigned a[4][4], bf[4][2];
#pragma unroll
            for (int mt = 0; mt < 4; mt++) {
                int rb = wm * 64 + mt * 16;
                a[mt][0] = As[s][(rb + g    ) * SSTR + ks + t    ];
                a[mt][1] = As[s][(rb + g + 8) * SSTR + ks + t    ];
                a[mt][2] = As[s][(rb + g    ) * SSTR + ks + t + 4];
                a[mt][3] = As[s][(rb + g + 8) * SSTR + ks + t + 4];
            }
#pragma unroll
            for (int nt = 0; nt < 4; nt++) {
                int cb = wn * 32 + nt * 8;
                bf[nt][0] = Bs[s][(cb + g) * SSTR + ks + t    ];
                bf[nt][1] = Bs[s][(cb + g) * SSTR + ks + t + 4];
            }
#pragma unroll
            for (int mt = 0; mt < 4; mt++)
#pragma unroll
                for (int nt = 0; nt < 4; nt++)
                    mma_tf32(c[mt][nt], a[mt], bf[nt][0], bf[nt][1]);
        }
        s ^= 1;
    }

#pragma unroll
    for (int mt = 0; mt < 4; mt++) {
#pragma unroll
        for (int nt = 0; nt < 4; nt++) {
            int r  = row0 + wm * 64 + mt * 16 + g;
            int cc = col0 + wn * 32 + nt * 8 + 2 * t;
            float2 lo = make_float2(c[mt][nt][0], c[mt][nt][1]);
            float2 hi = make_float2(c[mt][nt][2], c[mt][nt][3]);
            *(float2*)&C[(size_t)r * N + cc]       = lo;
            *(float2*)&C[(size_t)(r + 8) * N + cc] = hi;
        }
    }
}

// Fused QKV projection: grid.x in [0,24): 16 Wq tiles, 4 Wk tiles, 4 Wv tiles.
__global__ __launch_bounds__(256) void qkv_gemm(
    const float* __restrict__ hidden,
    const float* __restrict__ Wq, const float* __restrict__ Wk,
    const float* __restrict__ Wv,
    float* __restrict__ Qb, float* __restrict__ Kb, float* __restrict__ Vb)
{
    const int bx = blockIdx.x;
    const float* B;
    float* C;
    int Nc, col0;
    if (bx < 16)      { B = Wq; C = Qb; Nc = QC; col0 = bx * 128; }
    else if (bx < 20) { B = Wk; C = Kb; Nc = KC; col0 = (bx - 16) * 128; }
    else              { B = Wv; C = Vb; Nc = KC; col0 = (bx - 20) * 128; }
    gemm_tile(hidden, B, C, Nc, Dm, blockIdx.y * 128, col0);
}

__global__ __launch_bounds__(256) void gemm_tf32_db(
    const float* __restrict__ A, const float* __restrict__ B,
    float* __restrict__ C, int N, int K)
{
    gemm_tile(A, B, C, N, K, blockIdx.y * 128, blockIdx.x * 128);
}

// ---------------------------------------------------------------------------
// In-place RoPE (unchanged)
// ---------------------------------------------------------------------------
__global__ void rope_kernel(float* __restrict__ X,
                            const float* __restrict__ cosb,
                            const float* __restrict__ sinb,
                            int C, int total_pairs)
{
    int idx = blockIdx.x * blockDim.x + threadIdx.x;
    if (idx >= total_pairs) return;
    int per_row = C >> 1;
    int row  = idx / per_row;
    int p    = idx - row * per_row;
    int head = p >> 5;
    int d    = p & 31;
    int col1 = head * 64 + d;
    int col2 = col1 + 32;

    float c1 = cosb[row * 64 + d];
    float s1 = sinb[row * 64 + d];
    float c2 = cosb[row * 64 + d + 32];
    float s2 = sinb[row * 64 + d + 32];

    size_t base = (size_t)row * C;
    float x1 = X[base + col1];
    float x2 = X[base + col2];
    X[base + col1] = x1 * c1 - x2 * s1;
    X[base + col2] = x2 * c2 + x1 * s2;
}

// ---------------------------------------------------------------------------
// Flash attention v4: tf32 tensor cores, 128-row q tile, 8 warps.
// Block = (qt2, h, b). Warp w owns q rows w*16..w*16+15 (halves g, g+8).
// 64x64 K/V tiles -> K/V traffic halved vs 64-row q tile.
// Smem: Qt[d][q] (136 stride), Pt[j][q] (136), Kt[d][j] (72), Vs[j][d] (72).
// ---------------------------------------------------------------------------
#define FSK 72
#define FSQ 136

__global__ __launch_bounds__(256) void flash4_kernel(
    const float* __restrict__ Q, const float* __restrict__ K,
    const float* __restrict__ V, float* __restrict__ O)
{
    const int qt2 = blockIdx.x;
    const int h   = blockIdx.y;
    const int b   = blockIdx.z;
    const int kvh = h >> 2;

    extern __shared__ unsigned smu[];
    unsigned* Qt = smu;                      // 64*FSQ
    unsigned* Pt = smu + 64 * FSQ;           // 64*FSQ
    unsigned* Kt = smu + 2 * 64 * FSQ;       // 64*FSK
    unsigned* Vs = smu + 2 * 64 * FSQ + 64 * FSK;

    const int tid  = threadIdx.x;
    const int w    = tid >> 5;
    const int lane = tid & 31;
    const int g    = lane >> 2;
    const int t    = lane & 3;
    const int q0   = qt2 * 128;

    // Load Q tile (128 rows) transposed as tf32: Qt[d][q]
    {
        int r  = tid >> 1;
        int d0 = (tid & 1) * 32;
        const float* qg = &Q[(size_t)(b * Sq + q0 + r) * QC + h * DH + d0];
#pragma unroll
        for (int i = 0; i < 8; i++) {
            float4 v = *(const float4*)(qg + i * 4);
            Qt[(d0 + i * 4 + 0) * FSQ + r] = f2tf32(v.x);
            Qt[(d0 + i * 4 + 1) * FSQ + r] = f2tf32(v.y);
            Qt[(d0 + i * 4 + 2) * FSQ + r] = f2tf32(v.z);
            Qt[(d0 + i * 4 + 3) * FSQ + r] = f2tf32(v.w);
        }
    }

    float m0 = -1e30f, m1 = -1e30f, l0 = 0.f, l1 = 0.f;
    float acc[8][4];
#pragma unroll
    for (int nt = 0; nt < 8; nt++)
#pragma unroll
        for (int i = 0; i < 4; i++) acc[nt][i] = 0.f;

    const int r0   = q0 + w * 16 + g;    // global q row (low half)
    const int r1   = r0 + 8;
    const int wmax = q0 + w * 16 + 15;   // max q row this warp owns

    const int ktmax = qt2 * 2 + 1;
    for (int kt = 0; kt <= ktmax; ++kt) {
        const int k0 = kt * 64;
        __syncthreads();   // all warps done reading prev Kt/Vs (covers Qt iter 0)

        // Load K transposed (Kt[d][j]) and V natural (Vs[j][d]), tf32
        {
            int r  = tid >> 2;
            int d0 = (tid & 3) * 16;
            const float* kg = &K[(size_t)(b * Sq + k0 + r) * KC + kvh * DH + d0];
            const float* vg = &V[(size_t)(b * Sq + k0 + r) * KC + kvh * DH + d0];
#pragma unroll
            for (int i = 0; i < 4; i++) {
                float4 kv = *(const float4*)(kg + i * 4);
                Kt[(d0 + i * 4 + 0) * FSK + r] = f2tf32(kv.x);
                Kt[(d0 + i * 4 + 1) * FSK + r] = f2tf32(kv.y);
                Kt[(d0 + i * 4 + 2) * FSK + r] = f2tf32(kv.z);
                Kt[(d0 + i * 4 + 3) * FSK + r] = f2tf32(kv.w);
                float4 vv = *(const float4*)(vg + i * 4);
                *(uint4*)&Vs[r * FSK + d0 + i * 4] = cvt4(vv);
            }
        }
        __syncthreads();

        if (k0 > wmax) continue;   // tile fully masked for this warp

        // ---- S = Q K^T (16x64 per warp) ----
        float sc[8][4];
#pragma unroll
        for (int nt = 0; nt < 8; nt++)
#pragma unroll
            for (int i = 0; i < 4; i++) sc[nt][i] = 0.f;

#pragma unroll
        for (int ks = 0; ks < 8; ks++) {
            unsigned a[4];
            a[0] = Qt[(ks * 8 + t    ) * FSQ + w * 16 + g    ];
            a[1] = Qt[(ks * 8 + t    ) * FSQ + w * 16 + g + 8];
            a[2] = Qt[(ks * 8 + t + 4) * FSQ + w * 16 + g    ];
            a[3] = Qt[(ks * 8 + t + 4) * FSQ + w * 16 + g + 8];
#pragma unroll
            for (int nt = 0; nt < 8; nt++) {
                unsigned b0 = Kt[(ks * 8 + t    ) * FSK + nt * 8 + g];
                unsigned b1 = Kt[(ks * 8 + t + 4) * FSK + nt * 8 + g];
                mma_tf32(sc[nt], a, b0, b1);
            }
        }

        // ---- softmax on C frags ----
        const bool need_mask = (k0 + 63 > r0);
        float rmax0 = -1e30f, rmax1 = -1e30f;
#pragma unroll
        for (int nt = 0; nt < 8; nt++) {
#pragma unroll
            for (int c2 = 0; c2 < 2; c2++) {
                float v0 = sc[nt][c2    ] * 0.125f;
                float v1 = sc[nt][c2 + 2] * 0.125f;
                if (need_mask) {
                    int kj = k0 + nt * 8 + 2 * t + c2;
                    if (kj > r0) v0 = -1e30f;
                    if (kj > r1) v1 = -1e30f;
                }
                sc[nt][c2    ] = v0;
                sc[nt][c2 + 2] = v1;
                rmax0 = fmaxf(rmax0, v0);
                rmax1 = fmaxf(rmax1, v1);
            }
        }
        rmax0 = fmaxf(rmax0, __shfl_xor_sync(0xffffffffu, rmax0, 1));
        rmax0 = fmaxf(rmax0, __shfl_xor_sync(0xffffffffu, rmax0, 2));
        rmax1 = fmaxf(rmax1, __shfl_xor_sync(0xffffffffu, rmax1, 1));
        rmax1 = fmaxf(rmax1, __shfl_xor_sync(0xffffffffu, rmax1, 2));

        float mn0 = fmaxf(m0, rmax0), mn1 = fmaxf(m1, rmax1);
        float corr0 = __expf(m0 - mn0), corr1 = __expf(m1 - mn1);
        m0 = mn0; m1 = mn1;

        float ls0 = 0.f, ls1 = 0.f;
#pragma unroll
        for (int nt = 0; nt < 8; nt++) {
#pragma unroll
            for (int c2 = 0; c2 < 2; c2++) {
                float p0 = __expf(sc[nt][c2    ] - mn0);
                float p1 = __expf(sc[nt][c2 + 2] - mn1);
                ls0 += p0; ls1 += p1;
                Pt[(nt * 8 + 2 * t + c2) * FSQ + w * 16 + g    ] = f2tf32(p0);
                Pt[(nt * 8 + 2 * t + c2) * FSQ + w * 16 + g + 8] = f2tf32(p1);
            }
        }
        ls0 += __shfl_xor_sync(0xffffffffu, ls0, 1);
        ls0 += __shfl_xor_sync(0xffffffffu, ls0, 2);
        ls1 += __shfl_xor_sync(0xffffffffu, ls1, 1);
        ls1 += __shfl_xor_sync(0xffffffffu, ls1, 2);
        l0 = l0 * corr0 + ls0;
        l1 = l1 * corr1 + ls1;

#pragma unroll
        for (int nt = 0; nt < 8; nt++) {
            acc[nt][0] *= corr0; acc[nt][1] *= corr0;
            acc[nt][2] *= corr1; acc[nt][3] *= corr1;
        }

        __syncwarp();   // Pt columns are warp-local: order STS before LDS

        // ---- acc += P V (16x64 per warp) ----
#pragma unroll
        for (int ks = 0; ks < 8; ks++) {
            unsigned a[4];
            a[0] = Pt[(ks * 8 + t    ) * FSQ + w * 16 + g    ];
            a[1] = Pt[(ks * 8 + t    ) * FSQ + w * 16 + g + 8];
            a[2] = Pt[(ks * 8 + t + 4) * FSQ + w * 16 + g    ];
            a[3] = Pt[(ks * 8 + t + 4) * FSQ + w * 16 + g + 8];
#pragma unroll
            for (int nt = 0; nt < 8; nt++) {
                unsigned b0 = Vs[(ks * 8 + t    ) * FSK + nt * 8 + g];
                unsigned b1 = Vs[(ks * 8 + t + 4) * FSK + nt * 8 + g];
                mma_tf32(acc[nt], a, b0, b1);
            }
        }
    }

    // Epilogue
    float inv0 = 1.f / l0, inv1 = 1.f / l1;
    size_t orow0 = (size_t)(b * Sq + q0 + w * 16 + g) * QC;
    size_t orow1 = orow0 + 8 * (size_t)QC;
#pragma unroll
    for (int nt = 0; nt < 8; nt++) {
        int col = h * DH + nt * 8 + 2 * t;
        float2 lo = make_float2(acc[nt][0] * inv0, acc[nt][1] * inv0);
        float2 hi = make_float2(acc[nt][2] * inv1, acc[nt][3] * inv1);
        *(float2*)&O[orow0 + col] = lo;
        *(float2*)&O[orow1 + col] = hi;
    }
}

// ---------------------------------------------------------------------------
// kernel_launch
// ---------------------------------------------------------------------------
extern "C" void kernel_launch(void* const* d_in, const int* in_sizes, int n_in,
                              void* d_out, int out_size)
{
    const float* hidden = (const float*)d_in[0];
    const float* cosb   = (const float*)d_in[1];
    const float* sinb   = (const float*)d_in[2];
    const float* Wq     = (const float*)d_in[4];
    const float* Wk     = (const float*)d_in[5];
    const float* Wv     = (const float*)d_in[6];
    const float* Wo     = (const float*)d_in[7];
    float* out = (float*)d_out;

    float *Qb, *Kb, *Vb, *Ob;
    cudaGetSymbolAddress((void**)&Qb, g_Q);
    cudaGetSymbolAddress((void**)&Kb, g_K);
    cudaGetSymbolAddress((void**)&Vb, g_V);
    cudaGetSymbolAddress((void**)&Ob, g_O);

    // Fused QKV projections
    qkv_gemm<<<dim3(24, ROWS / 128), 256>>>(hidden, Wq, Wk, Wv, Qb, Kb, Vb);

    // RoPE on Q and K
    {
        int pq = ROWS * (QC / 2);
        rope_kernel<<<(pq + 255) / 256, 256>>>(Qb, cosb, sinb, QC, pq);
        int pk = ROWS * (KC / 2);
        rope_kernel<<<(pk + 255) / 256, 256>>>(Kb, cosb, sinb, KC, pk);
    }

    // Flash attention (tf32 tensor cores, 128-row q tiles)
    {
        int smem_bytes = (2 * 64 * FSQ + 2 * 64 * FSK) * (int)sizeof(unsigned);  // 106496
        cudaFuncSetAttribute(flash4_kernel,
            cudaFuncAttributeMaxDynamicSharedMemorySize, smem_bytes);
        dim3 grid(Sq / 128, Hh, Bsz);
        flash4_kernel<<<grid, 256, smem_bytes>>>(Qb, Kb, Vb, Ob);
    }

    // Output projection
    gemm_tf32_db<<<dim3(Dm / 128, ROWS / 128), 256>>>(Ob, Wo, out, Dm, Dm);
}

// round 7
// speedup vs baseline: 6.4738x; 1.1158x over previous
#include <cuda_runtime.h>
#include <cuda_bf16.h>
#include <math.h>

// Problem constants
#define Bsz 2
#define Sq  2048
#define Dm  2048
#define Hh  32
#define KVH 8
#define DH  64
#define ROWS (Bsz*Sq)  // 4096
#define QC  (Hh*DH)    // 2048
#define KC  (KVH*DH)   // 512

// Scratch buffers
__device__ float g_Q[(size_t)ROWS * QC];
__device__ float g_K[(size_t)ROWS * KC];
__device__ float g_V[(size_t)ROWS * KC];
__device__ float g_O[(size_t)ROWS * QC];

__device__ __forceinline__ unsigned f2tf32(float x) {
    unsigned r;
    asm("cvt.rna.tf32.f32 %0, %1;" : "=r"(r) : "f"(x));
    return r;
}

__device__ __forceinline__ uint4 cvt4(float4 v) {
    return make_uint4(f2tf32(v.x), f2tf32(v.y), f2tf32(v.z), f2tf32(v.w));
}

__device__ __forceinline__ unsigned s2u(const void* p) {
    return (unsigned)__cvta_generic_to_shared(p);
}

// ldmatrix x4: four 8-row x 16-byte matrices; thread L gets word [L/4][L%4]
// of each matrix -> exactly the tf32 mma fragment layout.
__device__ __forceinline__ void ldsm4(unsigned& r0, unsigned& r1,
                                      unsigned& r2, unsigned& r3,
                                      unsigned saddr) {
    asm volatile(
        "ldmatrix.sync.aligned.m8n8.x4.shared.b16 {%0,%1,%2,%3}, [%4];"
        : "=r"(r0), "=r"(r1), "=r"(r2), "=r"(r3) : "r"(saddr));
}

__device__ __forceinline__ void mma_tf32(float* c, const unsigned* a,
                                         unsigned b0, unsigned b1) {
    asm volatile(
        "mma.sync.aligned.m16n8k8.row.col.f32.tf32.tf32.f32 "
        "{%0,%1,%2,%3}, {%4,%5,%6,%7}, {%8,%9}, {%0,%1,%2,%3};\n"
        : "+f"(c[0]), "+f"(c[1]), "+f"(c[2]), "+f"(c[3])
        : "r"(a[0]), "r"(a[1]), "r"(a[2]), "r"(a[3]), "r"(b0), "r"(b1));
}

// ---------------------------------------------------------------------------
// Double-buffered tf32 GEMM tile with ldmatrix fragment loads.
// C[.,N] tile (row0,col0) = A[M,K]*B[N,K]^T. 128x128 tile, BK=16, 256 thr.
// ---------------------------------------------------------------------------
#define SSTR 20   // 5 x 16B units/row; 5i mod 8 distinct -> ldmatrix conflict-free

__device__ __forceinline__ void gemm_tile(
    const float* __restrict__ A, const float* __restrict__ B,
    float* __restrict__ C, int N, int K, int row0, int col0)
{
    __shared__ unsigned As[2][128 * SSTR];
    __shared__ unsigned Bs[2][128 * SSTR];

    const int tid  = threadIdx.x;
    const int wid  = tid >> 5;
    const int lane = tid & 31;
    const int g    = lane >> 2;
    const int t    = lane & 3;
    const int wm   = wid & 1;
    const int wn   = wid >> 1;

    // ldmatrix per-lane row/col offsets
    const int rowA = (lane & 7) + ((lane >> 3) & 1) * 8;  // A: m0/m2 rows 0-7, m1/m3 rows 8-15
    const int colA = (lane >> 4) * 4;                     //    m2/m3 at col +4
    const int rowB = (lane & 7) + (lane >> 4) * 8;        // B: m0/m1 rows 0-7, m2/m3 rows 8-15
    const int colB = ((lane >> 3) & 1) * 4;               //    m1/m3 at col +4

    int rr[2], kk[2];
    float4 pa[2], pb[2];
#pragma unroll
    for (int it = 0; it < 2; it++) {
        int idx = tid + it * 256;
        rr[it] = idx >> 2;
        kk[it] = (idx & 3) * 4;
        pa[it] = *(const float4*)&A[(size_t)(row0 + rr[it]) * K + kk[it]];
        pb[it] = *(const float4*)&B[(size_t)(col0 + rr[it]) * K + kk[it]];
    }

    float c[4][4][4];
#pragma unroll
    for (int mt = 0; mt < 4; mt++)
#pragma unroll
        for (int nt = 0; nt < 4; nt++)
#pragma unroll
            for (int i = 0; i < 4; i++) c[mt][nt][i] = 0.f;

    int s = 0;
    for (int kc = 0; kc < K; kc += 16) {
#pragma unroll
        for (int it = 0; it < 2; it++) {
            *(uint4*)&As[s][rr[it] * SSTR + kk[it]] = cvt4(pa[it]);
            *(uint4*)&Bs[s][rr[it] * SSTR + kk[it]] = cvt4(pb[it]);
        }
        __syncthreads();

        if (kc + 16 < K) {
#pragma unroll
            for (int it = 0; it < 2; it++) {
                pa[it] = *(const float4*)&A[(size_t)(row0 + rr[it]) * K + kc + 16 + kk[it]];
                pb[it] = *(const float4*)&B[(size_t)(col0 + rr[it]) * K + kc + 16 + kk[it]];
            }
        }

#pragma unroll
        for (int ks = 0; ks < 16; ks += 8) {
            unsigned a[4][4], bf[4][2];
#pragma unroll
            for (int mt = 0; mt < 4; mt++)
                ldsm4(a[mt][0], a[mt][1], a[mt][2], a[mt][3],
                      s2u(&As[s][(wm * 64 + mt * 16 + rowA) * SSTR + ks + colA]));
#pragma unroll
            for (int p = 0; p < 2; p++) {
                unsigned r0, r1, r2, r3;
                ldsm4(r0, r1, r2, r3,
                      s2u(&Bs[s][(wn * 32 + p * 16 + rowB) * SSTR + ks + colB]));
                bf[2 * p][0] = r0; bf[2 * p][1] = r1;
                bf[2 * p + 1][0] = r2; bf[2 * p + 1][1] = r3;
            }
#pragma unroll
            for (int mt = 0; mt < 4; mt++)
#pragma unroll
                for (int nt = 0; nt < 4; nt++)
                    mma_tf32(c[mt][nt], a[mt], bf[nt][0], bf[nt][1]);
        }
        s ^= 1;
    }

#pragma unroll
    for (int mt = 0; mt < 4; mt++) {
#pragma unroll
        for (int nt = 0; nt < 4; nt++) {
            int r  = row0 + wm * 64 + mt * 16 + g;
            int cc = col0 + wn * 32 + nt * 8 + 2 * t;
            float2 lo = make_float2(c[mt][nt][0], c[mt][nt][1]);
            float2 hi = make_float2(c[mt][nt][2], c[mt][nt][3]);
            *(float2*)&C[(size_t)r * N + cc]       = lo;
            *(float2*)&C[(size_t)(r + 8) * N + cc] = hi;
        }
    }
}

// Fused QKV projection: grid.x in [0,24): 16 Wq tiles, 4 Wk tiles, 4 Wv tiles.
__global__ __launch_bounds__(256) void qkv_gemm(
    const float* __restrict__ hidden,
    const float* __restrict__ Wq, const float* __restrict__ Wk,
    const float* __restrict__ Wv,
    float* __restrict__ Qb, float* __restrict__ Kb, float* __restrict__ Vb)
{
    const int bx = blockIdx.x;
    const float* B;
    float* C;
    int Nc, col0;
    if (bx < 16)      { B = Wq; C = Qb; Nc = QC; col0 = bx * 128; }
    else if (bx < 20) { B = Wk; C = Kb; Nc = KC; col0 = (bx - 16) * 128; }
    else              { B = Wv; C = Vb; Nc = KC; col0 = (bx - 20) * 128; }
    gemm_tile(hidden, B, C, Nc, Dm, blockIdx.y * 128, col0);
}

__global__ __launch_bounds__(256) void gemm_tf32_db(
    const float* __restrict__ A, const float* __restrict__ B,
    float* __restrict__ C, int N, int K)
{
    gemm_tile(A, B, C, N, K, blockIdx.y * 128, blockIdx.x * 128);
}

// ---------------------------------------------------------------------------
// In-place RoPE (unchanged)
// ---------------------------------------------------------------------------
__global__ void rope_kernel(float* __restrict__ X,
                            const float* __restrict__ cosb,
                            const float* __restrict__ sinb,
                            int C, int total_pairs)
{
    int idx = blockIdx.x * blockDim.x + threadIdx.x;
    if (idx >= total_pairs) return;
    int per_row = C >> 1;
    int row  = idx / per_row;
    int p    = idx - row * per_row;
    int head = p >> 5;
    int d    = p & 31;
    int col1 = head * 64 + d;
    int col2 = col1 + 32;

    float c1 = cosb[row * 64 + d];
    float s1 = sinb[row * 64 + d];
    float c2 = cosb[row * 64 + d + 32];
    float s2 = sinb[row * 64 + d + 32];

    size_t base = (size_t)row * C;
    float x1 = X[base + col1];
    float x2 = X[base + col2];
    X[base + col1] = x1 * c1 - x2 * s1;
    X[base + col2] = x2 * c2 + x1 * s2;
}

// ---------------------------------------------------------------------------
// Flash attention v6: all-tf32 (round-5 numerics), ldmatrix fragment loads.
// Block = (qt2, h, b), 256 threads = 8 warps; warp w owns q rows w*16..+15.
// Smem (stride FST=68 words = 17x16B units -> ldmatrix conflict-free):
//   Qs[q][d] 128xFST, Ps[q][j] 128xFST, Ks[j][d] 64xFST, Vt[d][j] 64xFST
// ---------------------------------------------------------------------------
#define FST 68
#define FLASH_SMEM_WORDS ((128 + 128 + 64 + 64) * FST)

__global__ __launch_bounds__(256) void flash6_kernel(
    const float* __restrict__ Q, const float* __restrict__ K,
    const float* __restrict__ V, float* __restrict__ O)
{
    const int qt2 = blockIdx.x;
    const int h   = blockIdx.y;
    const int b   = blockIdx.z;
    const int kvh = h >> 2;

    extern __shared__ unsigned smu[];
    unsigned* Qs = smu;                       // 128*FST
    unsigned* Ps = smu + 128 * FST;           // 128*FST
    unsigned* Ks = smu + 256 * FST;           // 64*FST
    unsigned* Vt = smu + 256 * FST + 64 * FST;// 64*FST

    const int tid  = threadIdx.x;
    const int w    = tid >> 5;
    const int lane = tid & 31;
    const int g    = lane >> 2;
    const int t    = lane & 3;
    const int q0   = qt2 * 128;

    const int rowA = (lane & 7) + ((lane >> 3) & 1) * 8;
    const int colA = (lane >> 4) * 4;
    const int rowB = (lane & 7) + (lane >> 4) * 8;
    const int colB = ((lane >> 3) & 1) * 4;

    // Load Q tile (128 rows) natural row-major as tf32 (vectorized stores)
    {
        int r  = tid >> 1;
        int d0 = (tid & 1) * 32;
        const float* qg = &Q[(size_t)(b * Sq + q0 + r) * QC + h * DH + d0];
#pragma unroll
        for (int i = 0; i < 8; i++)
            *(uint4*)&Qs[r * FST + d0 + i * 4] = cvt4(*(const float4*)(qg + i * 4));
    }

    float m0 = -1e30f, m1 = -1e30f, l0 = 0.f, l1 = 0.f;
    float acc[8][4];
#pragma unroll
    for (int nt = 0; nt < 8; nt++)
#pragma unroll
        for (int i = 0; i < 4; i++) acc[nt][i] = 0.f;

    const int r0   = q0 + w * 16 + g;
    const int r1   = r0 + 8;
    const int wmax = q0 + w * 16 + 15;

    const int ktmax = qt2 * 2 + 1;
    for (int kt = 0; kt <= ktmax; ++kt) {
        const int k0 = kt * 64;
        __syncthreads();   // all warps done reading prev Ks/Vt (covers Qs iter 0)

        // Load K natural (Ks[j][d], vectorized) and V transposed (Vt[d][j])
        {
            int r  = tid >> 2;
            int d0 = (tid & 3) * 16;
            const float* kg = &K[(size_t)(b * Sq + k0 + r) * KC + kvh * DH + d0];
            const float* vg = &V[(size_t)(b * Sq + k0 + r) * KC + kvh * DH + d0];
#pragma unroll
            for (int i = 0; i < 4; i++) {
                *(uint4*)&Ks[r * FST + d0 + i * 4] = cvt4(*(const float4*)(kg + i * 4));
                float4 vv = *(const float4*)(vg + i * 4);
                Vt[(d0 + i * 4 + 0) * FST + r] = f2tf32(vv.x);
                Vt[(d0 + i * 4 + 1) * FST + r] = f2tf32(vv.y);
                Vt[(d0 + i * 4 + 2) * FST + r] = f2tf32(vv.z);
                Vt[(d0 + i * 4 + 3) * FST + r] = f2tf32(vv.w);
            }
        }
        __syncthreads();

        if (k0 > wmax) continue;   // tile fully masked for this warp

        // ---- S = Q K^T (16x64 per warp, tf32, ldmatrix frags) ----
        float sc[8][4];
#pragma unroll
        for (int nt = 0; nt < 8; nt++)
#pragma unroll
            for (int i = 0; i < 4; i++) sc[nt][i] = 0.f;

#pragma unroll
        for (int ks = 0; ks < 8; ks++) {
            unsigned a[4];
            ldsm4(a[0], a[1], a[2], a[3],
                  s2u(&Qs[(w * 16 + rowA) * FST + ks * 8 + colA]));
#pragma unroll
            for (int p = 0; p < 4; p++) {
                unsigned b0, b1, b2, b3;
                ldsm4(b0, b1, b2, b3,
                      s2u(&Ks[(p * 16 + rowB) * FST + ks * 8 + colB]));
                mma_tf32(sc[2 * p],     a, b0, b1);
                mma_tf32(sc[2 * p + 1], a, b2, b3);
            }
        }

        // ---- softmax on C frags ----
        const bool need_mask = (k0 + 63 > r0);
        float rmax0 = -1e30f, rmax1 = -1e30f;
#pragma unroll
        for (int nt = 0; nt < 8; nt++) {
#pragma unroll
            for (int c2 = 0; c2 < 2; c2++) {
                float v0 = sc[nt][c2    ] * 0.125f;
                float v1 = sc[nt][c2 + 2] * 0.125f;
                if (need_mask) {
                    int kj = k0 + nt * 8 + 2 * t + c2;
                    if (kj > r0) v0 = -1e30f;
                    if (kj > r1) v1 = -1e30f;
                }
                sc[nt][c2    ] = v0;
                sc[nt][c2 + 2] = v1;
                rmax0 = fmaxf(rmax0, v0);
                rmax1 = fmaxf(rmax1, v1);
            }
        }
        rmax0 = fmaxf(rmax0, __shfl_xor_sync(0xffffffffu, rmax0, 1));
        rmax0 = fmaxf(rmax0, __shfl_xor_sync(0xffffffffu, rmax0, 2));
        rmax1 = fmaxf(rmax1, __shfl_xor_sync(0xffffffffu, rmax1, 1));
        rmax1 = fmaxf(rmax1, __shfl_xor_sync(0xffffffffu, rmax1, 2));

        float mn0 = fmaxf(m0, rmax0), mn1 = fmaxf(m1, rmax1);
        float corr0 = __expf(m0 - mn0), corr1 = __expf(m1 - mn1);
        m0 = mn0; m1 = mn1;

        float ls0 = 0.f, ls1 = 0.f;
#pragma unroll
        for (int nt = 0; nt < 8; nt++) {
#pragma unroll
            for (int c2 = 0; c2 < 2; c2++) {
                float p0 = __expf(sc[nt][c2    ] - mn0);
                float p1 = __expf(sc[nt][c2 + 2] - mn1);
                ls0 += p0; ls1 += p1;
                int jj = nt * 8 + 2 * t + c2;
                Ps[(w * 16 + g    ) * FST + jj] = f2tf32(p0);
                Ps[(w * 16 + g + 8) * FST + jj] = f2tf32(p1);
            }
        }
        ls0 += __shfl_xor_sync(0xffffffffu, ls0, 1);
        ls0 += __shfl_xor_sync(0xffffffffu, ls0, 2);
        ls1 += __shfl_xor_sync(0xffffffffu, ls1, 1);
        ls1 += __shfl_xor_sync(0xffffffffu, ls1, 2);
        l0 = l0 * corr0 + ls0;
        l1 = l1 * corr1 + ls1;

#pragma unroll
        for (int nt = 0; nt < 8; nt++) {
            acc[nt][0] *= corr0; acc[nt][1] *= corr0;
            acc[nt][2] *= corr1; acc[nt][3] *= corr1;
        }

        __syncwarp();   // Ps rows are warp-local: order STS before ldmatrix

        // ---- acc += P V (16x64 per warp, tf32, ldmatrix frags) ----
#pragma unroll
        for (int ks = 0; ks < 8; ks++) {
            unsigned a[4];
            ldsm4(a[0], a[1], a[2], a[3],
                  s2u(&Ps[(w * 16 + rowA) * FST + ks * 8 + colA]));
#pragma unroll
            for (int p = 0; p < 4; p++) {
                unsigned b0, b1, b2, b3;
                ldsm4(b0, b1, b2, b3,
                      s2u(&Vt[(p * 16 + rowB) * FST + ks * 8 + colB]));
                mma_tf32(acc[2 * p],     a, b0, b1);
                mma_tf32(acc[2 * p + 1], a, b2, b3);
            }
        }
    }

    // Epilogue
    float inv0 = 1.f / l0, inv1 = 1.f / l1;
    size_t orow0 = (size_t)(b * Sq + q0 + w * 16 + g) * QC;
    size_t orow1 = orow0 + 8 * (size_t)QC;
#pragma unroll
    for (int nt = 0; nt < 8; nt++) {
        int col = h * DH + nt * 8 + 2 * t;
        float2 lo = make_float2(acc[nt][0] * inv0, acc[nt][1] * inv0);
        float2 hi = make_float2(acc[nt][2] * inv1, acc[nt][3] * inv1);
        *(float2*)&O[orow0 + col] = lo;
        *(float2*)&O[orow1 + col] = hi;
    }
}

// ---------------------------------------------------------------------------
// kernel_launch
// ---------------------------------------------------------------------------
extern "C" void kernel_launch(void* const* d_in, const int* in_sizes, int n_in,
                              void* d_out, int out_size)
{
    const float* hidden = (const float*)d_in[0];
    const float* cosb   = (const float*)d_in[1];
    const float* sinb   = (const float*)d_in[2];
    const float* Wq     = (const float*)d_in[4];
    const float* Wk     = (const float*)d_in[5];
    const float* Wv     = (const float*)d_in[6];
    const float* Wo     = (const float*)d_in[7];
    float* out = (float*)d_out;

    float *Qb, *Kb, *Vb, *Ob;
    cudaGetSymbolAddress((void**)&Qb, g_Q);
    cudaGetSymbolAddress((void**)&Kb, g_K);
    cudaGetSymbolAddress((void**)&Vb, g_V);
    cudaGetSymbolAddress((void**)&Ob, g_O);

    // Fused QKV projections
    qkv_gemm<<<dim3(24, ROWS / 128), 256>>>(hidden, Wq, Wk, Wv, Qb, Kb, Vb);

    // RoPE on Q and K
    {
        int pq = ROWS * (QC / 2);
        rope_kernel<<<(pq + 255) / 256, 256>>>(Qb, cosb, sinb, QC, pq);
        int pk = ROWS * (KC / 2);
        rope_kernel<<<(pk + 255) / 256, 256>>>(Kb, cosb, sinb, KC, pk);
    }

    // Flash attention (all tf32, ldmatrix fragment loads)
    {
        int smem_bytes = FLASH_SMEM_WORDS * (int)sizeof(unsigned);  // 104448
        cudaFuncSetAttribute(flash6_kernel,
            cudaFuncAttributeMaxDynamicSharedMemorySize, smem_bytes);
        dim3 grid(Sq / 128, Hh, Bsz);
        flash6_kernel<<<grid, 256, smem_bytes>>>(Qb, Kb, Vb, Ob);
    }

    // Output projection
    gemm_tf32_db<<<dim3(Dm / 128, ROWS / 128), 256>>>(Ob, Wo, out, Dm, Dm);
}

// round 8
// speedup vs baseline: 6.7999x; 1.0504x over previous
#include <cuda_runtime.h>
#include <cuda_bf16.h>
#include <math.h>

// Problem constants
#define Bsz 2
#define Sq  2048
#define Dm  2048
#define Hh  32
#define KVH 8
#define DH  64
#define ROWS (Bsz*Sq)  // 4096
#define QC  (Hh*DH)    // 2048
#define KC  (KVH*DH)   // 512

// Scratch buffers
__device__ float g_Q[(size_t)ROWS * QC];
__device__ float g_K[(size_t)ROWS * KC];
__device__ float g_V[(size_t)ROWS * KC];
__device__ float g_O[(size_t)ROWS * QC];

__device__ __forceinline__ unsigned f2tf32(float x) {
    unsigned r;
    asm("cvt.rna.tf32.f32 %0, %1;" : "=r"(r) : "f"(x));
    return r;
}

__device__ __forceinline__ uint4 cvt4(float4 v) {
    return make_uint4(f2tf32(v.x), f2tf32(v.y), f2tf32(v.z), f2tf32(v.w));
}

__device__ __forceinline__ unsigned s2u(const void* p) {
    return (unsigned)__cvta_generic_to_shared(p);
}

__device__ __forceinline__ void ldsm4(unsigned& r0, unsigned& r1,
                                      unsigned& r2, unsigned& r3,
                                      unsigned saddr) {
    asm volatile(
        "ldmatrix.sync.aligned.m8n8.x4.shared.b16 {%0,%1,%2,%3}, [%4];"
        : "=r"(r0), "=r"(r1), "=r"(r2), "=r"(r3) : "r"(saddr));
}

__device__ __forceinline__ void mma_tf32(float* c, const unsigned* a,
                                         unsigned b0, unsigned b1) {
    asm volatile(
        "mma.sync.aligned.m16n8k8.row.col.f32.tf32.tf32.f32 "
        "{%0,%1,%2,%3}, {%4,%5,%6,%7}, {%8,%9}, {%0,%1,%2,%3};\n"
        : "+f"(c[0]), "+f"(c[1]), "+f"(c[2]), "+f"(c[3])
        : "r"(a[0]), "r"(a[1]), "r"(a[2]), "r"(a[3]), "r"(b0), "r"(b1));
}

// ---------------------------------------------------------------------------
// Double-buffered tf32 GEMM tile with ldmatrix fragment loads (unchanged).
// ---------------------------------------------------------------------------
#define SSTR 20

__device__ __forceinline__ void gemm_tile(
    const float* __restrict__ A, const float* __restrict__ B,
    float* __restrict__ C, int N, int K, int row0, int col0)
{
    __shared__ unsigned As[2][128 * SSTR];
    __shared__ unsigned Bs[2][128 * SSTR];

    const int tid  = threadIdx.x;
    const int wid  = tid >> 5;
    const int lane = tid & 31;
    const int g    = lane >> 2;
    const int t    = lane & 3;
    const int wm   = wid & 1;
    const int wn   = wid >> 1;

    const int rowA = (lane & 7) + ((lane >> 3) & 1) * 8;
    const int colA = (lane >> 4) * 4;
    const int rowB = (lane & 7) + (lane >> 4) * 8;
    const int colB = ((lane >> 3) & 1) * 4;

    int rr[2], kk[2];
    float4 pa[2], pb[2];
#pragma unroll
    for (int it = 0; it < 2; it++) {
        int idx = tid + it * 256;
        rr[it] = idx >> 2;
        kk[it] = (idx & 3) * 4;
        pa[it] = *(const float4*)&A[(size_t)(row0 + rr[it]) * K + kk[it]];
        pb[it] = *(const float4*)&B[(size_t)(col0 + rr[it]) * K + kk[it]];
    }

    float c[4][4][4];
#pragma unroll
    for (int mt = 0; mt < 4; mt++)
#pragma unroll
        for (int nt = 0; nt < 4; nt++)
#pragma unroll
            for (int i = 0; i < 4; i++) c[mt][nt][i] = 0.f;

    int s = 0;
    for (int kc = 0; kc < K; kc += 16) {
#pragma unroll
        for (int it = 0; it < 2; it++) {
            *(uint4*)&As[s][rr[it] * SSTR + kk[it]] = cvt4(pa[it]);
            *(uint4*)&Bs[s][rr[it] * SSTR + kk[it]] = cvt4(pb[it]);
        }
        __syncthreads();

        if (kc + 16 < K) {
#pragma unroll
            for (int it = 0; it < 2; it++) {
                pa[it] = *(const float4*)&A[(size_t)(row0 + rr[it]) * K + kc + 16 + kk[it]];
                pb[it] = *(const float4*)&B[(size_t)(col0 + rr[it]) * K + kc + 16 + kk[it]];
            }
        }

#pragma unroll
        for (int ks = 0; ks < 16; ks += 8) {
            unsigned a[4][4], bf[4][2];
#pragma unroll
            for (int mt = 0; mt < 4; mt++)
                ldsm4(a[mt][0], a[mt][1], a[mt][2], a[mt][3],
                      s2u(&As[s][(wm * 64 + mt * 16 + rowA) * SSTR + ks + colA]));
#pragma unroll
            for (int p = 0; p < 2; p++) {
                unsigned r0, r1, r2, r3;
                ldsm4(r0, r1, r2, r3,
                      s2u(&Bs[s][(wn * 32 + p * 16 + rowB) * SSTR + ks + colB]));
                bf[2 * p][0] = r0; bf[2 * p][1] = r1;
                bf[2 * p + 1][0] = r2; bf[2 * p + 1][1] = r3;
            }
#pragma unroll
            for (int mt = 0; mt < 4; mt++)
#pragma unroll
                for (int nt = 0; nt < 4; nt++)
                    mma_tf32(c[mt][nt], a[mt], bf[nt][0], bf[nt][1]);
        }
        s ^= 1;
    }

#pragma unroll
    for (int mt = 0; mt < 4; mt++) {
#pragma unroll
        for (int nt = 0; nt < 4; nt++) {
            int r  = row0 + wm * 64 + mt * 16 + g;
            int cc = col0 + wn * 32 + nt * 8 + 2 * t;
            float2 lo = make_float2(c[mt][nt][0], c[mt][nt][1]);
            float2 hi = make_float2(c[mt][nt][2], c[mt][nt][3]);
            *(float2*)&C[(size_t)r * N + cc]       = lo;
            *(float2*)&C[(size_t)(r + 8) * N + cc] = hi;
        }
    }
}

__global__ __launch_bounds__(256) void qkv_gemm(
    const float* __restrict__ hidden,
    const float* __restrict__ Wq, const float* __restrict__ Wk,
    const float* __restrict__ Wv,
    float* __restrict__ Qb, float* __restrict__ Kb, float* __restrict__ Vb)
{
    const int bx = blockIdx.x;
    const float* B;
    float* C;
    int Nc, col0;
    if (bx < 16)      { B = Wq; C = Qb; Nc = QC; col0 = bx * 128; }
    else if (bx < 20) { B = Wk; C = Kb; Nc = KC; col0 = (bx - 16) * 128; }
    else              { B = Wv; C = Vb; Nc = KC; col0 = (bx - 20) * 128; }
    gemm_tile(hidden, B, C, Nc, Dm, blockIdx.y * 128, col0);
}

__global__ __launch_bounds__(256) void gemm_tf32_db(
    const float* __restrict__ A, const float* __restrict__ B,
    float* __restrict__ C, int N, int K)
{
    gemm_tile(A, B, C, N, K, blockIdx.y * 128, blockIdx.x * 128);
}

// ---------------------------------------------------------------------------
// In-place RoPE (unchanged)
// ---------------------------------------------------------------------------
__global__ void rope_kernel(float* __restrict__ X,
                            const float* __restrict__ cosb,
                            const float* __restrict__ sinb,
                            int C, int total_pairs)
{
    int idx = blockIdx.x * blockDim.x + threadIdx.x;
    if (idx >= total_pairs) return;
    int per_row = C >> 1;
    int row  = idx / per_row;
    int p    = idx - row * per_row;
    int head = p >> 5;
    int d    = p & 31;
    int col1 = head * 64 + d;
    int col2 = col1 + 32;

    float c1 = cosb[row * 64 + d];
    float s1 = sinb[row * 64 + d];
    float c2 = cosb[row * 64 + d + 32];
    float s2 = sinb[row * 64 + d + 32];

    size_t base = (size_t)row * C;
    float x1 = X[base + col1];
    float x2 = X[base + col2];
    X[base + col1] = x1 * c1 - x2 * s1;
    X[base + col2] = x2 * c2 + x1 * s2;
}

// ---------------------------------------------------------------------------
// Flash attention v7: all-tf32, ldmatrix, 256-row q tile, 8 warps, each warp
// owns 32 q-rows (two m16 tiles) -> B-fragment traffic amortized 2x.
// Smem (stride FST=68): Qs[q][d] 256xFST, Ps[q][j] 256xFST,
//                       Ks[j][d] 64xFST,  Vt[d][j] 64xFST   (174 KB)
// ---------------------------------------------------------------------------
#define QT  256
#define FST 68
#define FLASH_SMEM_WORDS ((QT + QT + 64 + 64) * FST)

__global__ __launch_bounds__(256, 1) void flash7_kernel(
    const float* __restrict__ Q, const float* __restrict__ K,
    const float* __restrict__ V, float* __restrict__ O)
{
    const int qt2 = (Sq / QT - 1) - blockIdx.x;   // big blocks first
    const int h   = blockIdx.y;
    const int b   = blockIdx.z;
    const int kvh = h >> 2;

    extern __shared__ unsigned smu[];
    unsigned* Qs = smu;                         // QT*FST
    unsigned* Ps = smu + QT * FST;              // QT*FST
    unsigned* Ks = smu + 2 * QT * FST;          // 64*FST
    unsigned* Vt = smu + 2 * QT * FST + 64 * FST;

    const int tid  = threadIdx.x;
    const int w    = tid >> 5;
    const int lane = tid & 31;
    const int g    = lane >> 2;
    const int t    = lane & 3;
    const int q0   = qt2 * QT;
    const int wb   = w * 32;                    // warp row base within tile

    const int rowA = (lane & 7) + ((lane >> 3) & 1) * 8;
    const int colA = (lane >> 4) * 4;
    const int rowB = (lane & 7) + (lane >> 4) * 8;
    const int colB = ((lane >> 3) & 1) * 4;

    // Load Q tile (QT rows): one row per thread, vectorized tf32 stores
    {
        const float* qg = &Q[(size_t)(b * Sq + q0 + tid) * QC + h * DH];
#pragma unroll
        for (int i = 0; i < 16; i++)
            *(uint4*)&Qs[tid * FST + i * 4] = cvt4(*(const float4*)(qg + i * 4));
    }

    // Per-warp state: index [mt*2 + half]
    float m[4], l[4];
#pragma unroll
    for (int i = 0; i < 4; i++) { m[i] = -1e30f; l[i] = 0.f; }
    float acc[2][8][4];
#pragma unroll
    for (int mt = 0; mt < 2; mt++)
#pragma unroll
        for (int nt = 0; nt < 8; nt++)
#pragma unroll
            for (int i = 0; i < 4; i++) acc[mt][nt][i] = 0.f;

    const int wmax = q0 + wb + 31;

    const int ktmax = (q0 + QT - 1) / 64;
    for (int kt = 0; kt <= ktmax; ++kt) {
        const int k0 = kt * 64;
        __syncthreads();   // all warps done reading prev Ks/Vt (covers Qs iter 0)

        // Load K natural (Ks[j][d]) and V transposed (Vt[d][j]) as tf32
        {
            int r  = tid >> 2;
            int d0 = (tid & 3) * 16;
            const float* kg = &K[(size_t)(b * Sq + k0 + r) * KC + kvh * DH + d0];
            const float* vg = &V[(size_t)(b * Sq + k0 + r) * KC + kvh * DH + d0];
#pragma unroll
            for (int i = 0; i < 4; i++) {
                *(uint4*)&Ks[r * FST + d0 + i * 4] = cvt4(*(const float4*)(kg + i * 4));
                float4 vv = *(const float4*)(vg + i * 4);
                Vt[(d0 + i * 4 + 0) * FST + r] = f2tf32(vv.x);
                Vt[(d0 + i * 4 + 1) * FST + r] = f2tf32(vv.y);
                Vt[(d0 + i * 4 + 2) * FST + r] = f2tf32(vv.z);
                Vt[(d0 + i * 4 + 3) * FST + r] = f2tf32(vv.w);
            }
        }
        __syncthreads();

        if (k0 > wmax) continue;   // tile fully masked for this warp's 32 rows

        // ---- S = Q K^T (32x64 per warp: 2 m-tiles share each B frag) ----
        float sc[2][8][4];
#pragma unroll
        for (int mt = 0; mt < 2; mt++)
#pragma unroll
            for (int nt = 0; nt < 8; nt++)
#pragma unroll
                for (int i = 0; i < 4; i++) sc[mt][nt][i] = 0.f;

#pragma unroll
        for (int ks = 0; ks < 8; ks++) {
            unsigned a[2][4];
#pragma unroll
            for (int mt = 0; mt < 2; mt++)
                ldsm4(a[mt][0], a[mt][1], a[mt][2], a[mt][3],
                      s2u(&Qs[(wb + mt * 16 + rowA) * FST + ks * 8 + colA]));
#pragma unroll
            for (int p = 0; p < 4; p++) {
                unsigned b0, b1, b2, b3;
                ldsm4(b0, b1, b2, b3,
                      s2u(&Ks[(p * 16 + rowB) * FST + ks * 8 + colB]));
#pragma unroll
                for (int mt = 0; mt < 2; mt++) {
                    mma_tf32(sc[mt][2 * p],     a[mt], b0, b1);
                    mma_tf32(sc[mt][2 * p + 1], a[mt], b2, b3);
                }
            }
        }

        // ---- softmax on C frags (per m-tile) ----
#pragma unroll
        for (int mt = 0; mt < 2; mt++) {
            const int rlo = q0 + wb + mt * 16 + g;
            const int rhi = rlo + 8;
            const bool need_mask = (k0 + 63 > rlo);
            float rmax0 = -1e30f, rmax1 = -1e30f;
#pragma unroll
            for (int nt = 0; nt < 8; nt++) {
#pragma unroll
                for (int c2 = 0; c2 < 2; c2++) {
                    float v0 = sc[mt][nt][c2    ] * 0.125f;
                    float v1 = sc[mt][nt][c2 + 2] * 0.125f;
                    if (need_mask) {
                        int kj = k0 + nt * 8 + 2 * t + c2;
                        if (kj > rlo) v0 = -1e30f;
                        if (kj > rhi) v1 = -1e30f;
                    }
                    sc[mt][nt][c2    ] = v0;
                    sc[mt][nt][c2 + 2] = v1;
                    rmax0 = fmaxf(rmax0, v0);
                    rmax1 = fmaxf(rmax1, v1);
                }
            }
            rmax0 = fmaxf(rmax0, __shfl_xor_sync(0xffffffffu, rmax0, 1));
            rmax0 = fmaxf(rmax0, __shfl_xor_sync(0xffffffffu, rmax0, 2));
            rmax1 = fmaxf(rmax1, __shfl_xor_sync(0xffffffffu, rmax1, 1));
            rmax1 = fmaxf(rmax1, __shfl_xor_sync(0xffffffffu, rmax1, 2));

            float mn0 = fmaxf(m[mt * 2],     rmax0);
            float mn1 = fmaxf(m[mt * 2 + 1], rmax1);
            float corr0 = __expf(m[mt * 2]     - mn0);
            float corr1 = __expf(m[mt * 2 + 1] - mn1);
            m[mt * 2] = mn0; m[mt * 2 + 1] = mn1;

            float ls0 = 0.f, ls1 = 0.f;
#pragma unroll
            for (int nt = 0; nt < 8; nt++) {
#pragma unroll
                for (int c2 = 0; c2 < 2; c2++) {
                    float p0 = __expf(sc[mt][nt][c2    ] - mn0);
                    float p1 = __expf(sc[mt][nt][c2 + 2] - mn1);
                    ls0 += p0; ls1 += p1;
                    int jj = nt * 8 + 2 * t + c2;
                    Ps[(wb + mt * 16 + g    ) * FST + jj] = f2tf32(p0);
                    Ps[(wb + mt * 16 + g + 8) * FST + jj] = f2tf32(p1);
                }
            }
            ls0 += __shfl_xor_sync(0xffffffffu, ls0, 1);
            ls0 += __shfl_xor_sync(0xffffffffu, ls0, 2);
            ls1 += __shfl_xor_sync(0xffffffffu, ls1, 1);
            ls1 += __shfl_xor_sync(0xffffffffu, ls1, 2);
            l[mt * 2]     = l[mt * 2]     * corr0 + ls0;
            l[mt * 2 + 1] = l[mt * 2 + 1] * corr1 + ls1;

#pragma unroll
            for (int nt = 0; nt < 8; nt++) {
                acc[mt][nt][0] *= corr0; acc[mt][nt][1] *= corr0;
                acc[mt][nt][2] *= corr1; acc[mt][nt][3] *= corr1;
            }
        }

        __syncwarp();   // Ps rows are warp-local: order STS before ldmatrix

        // ---- acc += P V (32x64 per warp, B frags shared by both m-tiles) ----
#pragma unroll
        for (int ks = 0; ks < 8; ks++) {
            unsigned a[2][4];
#pragma unroll
            for (int mt = 0; mt < 2; mt++)
                ldsm4(a[mt][0], a[mt][1], a[mt][2], a[mt][3],
                      s2u(&Ps[(wb + mt * 16 + rowA) * FST + ks * 8 + colA]));
#pragma unroll
            for (int p = 0; p < 4; p++) {
                unsigned b0, b1, b2, b3;
                ldsm4(b0, b1, b2, b3,
                      s2u(&Vt[(p * 16 + rowB) * FST + ks * 8 + colB]));
#pragma unroll
                for (int mt = 0; mt < 2; mt++) {
                    mma_tf32(acc[mt][2 * p],     a[mt], b0, b1);
                    mma_tf32(acc[mt][2 * p + 1], a[mt], b2, b3);
                }
            }
        }
    }

    // Epilogue
#pragma unroll
    for (int mt = 0; mt < 2; mt++) {
        float inv0 = 1.f / l[mt * 2];
        float inv1 = 1.f / l[mt * 2 + 1];
        size_t orow0 = (size_t)(b * Sq + q0 + wb + mt * 16 + g) * QC;
        size_t orow1 = orow0 + 8 * (size_t)QC;
#pragma unroll
        for (int nt = 0; nt < 8; nt++) {
            int col = h * DH + nt * 8 + 2 * t;
            float2 lo = make_float2(acc[mt][nt][0] * inv0, acc[mt][nt][1] * inv0);
            float2 hi = make_float2(acc[mt][nt][2] * inv1, acc[mt][nt][3] * inv1);
            *(float2*)&O[orow0 + col] = lo;
            *(float2*)&O[orow1 + col] = hi;
        }
    }
}

// ---------------------------------------------------------------------------
// kernel_launch
// ---------------------------------------------------------------------------
extern "C" void kernel_launch(void* const* d_in, const int* in_sizes, int n_in,
                              void* d_out, int out_size)
{
    const float* hidden = (const float*)d_in[0];
    const float* cosb   = (const float*)d_in[1];
    const float* sinb   = (const float*)d_in[2];
    const float* Wq     = (const float*)d_in[4];
    const float* Wk     = (const float*)d_in[5];
    const float* Wv     = (const float*)d_in[6];
    const float* Wo     = (const float*)d_in[7];
    float* out = (float*)d_out;

    float *Qb, *Kb, *Vb, *Ob;
    cudaGetSymbolAddress((void**)&Qb, g_Q);
    cudaGetSymbolAddress((void**)&Kb, g_K);
    cudaGetSymbolAddress((void**)&Vb, g_V);
    cudaGetSymbolAddress((void**)&Ob, g_O);

    // Fused QKV projections
    qkv_gemm<<<dim3(24, ROWS / 128), 256>>>(hidden, Wq, Wk, Wv, Qb, Kb, Vb);

    // RoPE on Q and K
    {
        int pq = ROWS * (QC / 2);
        rope_kernel<<<(pq + 255) / 256, 256>>>(Qb, cosb, sinb, QC, pq);
        int pk = ROWS * (KC / 2);
        rope_kernel<<<(pk + 255) / 256, 256>>>(Kb, cosb, sinb, KC, pk);
    }

    // Flash attention (tf32, 256-row q tiles, 32 rows/warp)
    {
        int smem_bytes = FLASH_SMEM_WORDS * (int)sizeof(unsigned);  // 174080
        cudaFuncSetAttribute(flash7_kernel,
            cudaFuncAttributeMaxDynamicSharedMemorySize, smem_bytes);
        dim3 grid(Sq / QT, Hh, Bsz);
        flash7_kernel<<<grid, 256, smem_bytes>>>(Qb, Kb, Vb, Ob);
    }

    // Output projection
    gemm_tf32_db<<<dim3(Dm / 128, ROWS / 128), 256>>>(Ob, Wo, out, Dm, Dm);
}

// round 9
// speedup vs baseline: 6.9648x; 1.0242x over previous
#include <cuda_runtime.h>
#include <cuda_bf16.h>
#include <math.h>

// Problem constants
#define Bsz 2
#define Sq  2048
#define Dm  2048
#define Hh  32
#define KVH 8
#define DH  64
#define ROWS (Bsz*Sq)  // 4096
#define QC  (Hh*DH)    // 2048
#define KC  (KVH*DH)   // 512

// Scratch buffers
__device__ float    g_Q [(size_t)ROWS * QC];   // rope writes tf32-rounded
__device__ float    g_K [(size_t)ROWS * KC];   // rope writes tf32-rounded
__device__ float    g_V [(size_t)ROWS * KC];
__device__ float    g_O [(size_t)ROWS * QC];   // flash writes tf32-rounded
__device__ unsigned g_h32 [(size_t)ROWS * Dm];
__device__ unsigned g_wq32[(size_t)QC * Dm];
__device__ unsigned g_wk32[(size_t)KC * Dm];
__device__ unsigned g_wv32[(size_t)KC * Dm];
__device__ unsigned g_wo32[(size_t)Dm * Dm];
__device__ unsigned g_Vt32[(size_t)Bsz * KC * Sq];  // V transposed, tf32

__device__ __forceinline__ unsigned f2tf32(float x) {
    unsigned r;
    asm("cvt.rna.tf32.f32 %0, %1;" : "=r"(r) : "f"(x));
    return r;
}

__device__ __forceinline__ uint4 cvt4(float4 v) {
    return make_uint4(f2tf32(v.x), f2tf32(v.y), f2tf32(v.z), f2tf32(v.w));
}

__device__ __forceinline__ unsigned s2u(const void* p) {
    return (unsigned)__cvta_generic_to_shared(p);
}

__device__ __forceinline__ void cp16(unsigned saddr, const void* gptr) {
    asm volatile("cp.async.cg.shared.global [%0], [%1], 16;"
                 :: "r"(saddr), "l"(gptr));
}
#define CP_COMMIT() asm volatile("cp.async.commit_group;")
#define CP_WAIT1()  asm volatile("cp.async.wait_group 1;")

__device__ __forceinline__ void ldsm4(unsigned& r0, unsigned& r1,
                                      unsigned& r2, unsigned& r3,
                                      unsigned saddr) {
    asm volatile(
        "ldmatrix.sync.aligned.m8n8.x4.shared.b16 {%0,%1,%2,%3}, [%4];"
        : "=r"(r0), "=r"(r1), "=r"(r2), "=r"(r3) : "r"(saddr));
}

__device__ __forceinline__ void mma_tf32(float* c, const unsigned* a,
                                         unsigned b0, unsigned b1) {
    asm volatile(
        "mma.sync.aligned.m16n8k8.row.col.f32.tf32.tf32.f32 "
        "{%0,%1,%2,%3}, {%4,%5,%6,%7}, {%8,%9}, {%0,%1,%2,%3};\n"
        : "+f"(c[0]), "+f"(c[1]), "+f"(c[2]), "+f"(c[3])
        : "r"(a[0]), "r"(a[1]), "r"(a[2]), "r"(a[3]), "r"(b0), "r"(b1));
}

// ---------------------------------------------------------------------------
// Elementwise float -> tf32-bit conversion
// ---------------------------------------------------------------------------
__global__ void cvt_tf32_kernel(const float4* __restrict__ src,
                                uint4* __restrict__ dst, int n4)
{
    int i = blockIdx.x * blockDim.x + threadIdx.x;
    if (i < n4) dst[i] = cvt4(src[i]);
}

// ---------------------------------------------------------------------------
// V transpose (per batch): [Sq][KC] -> [KC][Sq], tf32-rounded
// ---------------------------------------------------------------------------
__global__ void transpose_v_kernel(const float* __restrict__ V,
                                   unsigned* __restrict__ Vt)
{
    __shared__ float tile[32][33];
    int b  = blockIdx.z;
    int s0 = blockIdx.x * 32;
    int c0 = blockIdx.y * 32;
    int x = threadIdx.x, y = threadIdx.y;  // 32x8
#pragma unroll
    for (int i = 0; i < 4; i++)
        tile[y + 8 * i][x] = V[(size_t)(b * Sq + s0 + y + 8 * i) * KC + c0 + x];
    __syncthreads();
#pragma unroll
    for (int i = 0; i < 4; i++)
        Vt[(size_t)(b * KC + c0 + y + 8 * i) * Sq + s0 + x] =
            f2tf32(tile[x][y + 8 * i]);
}

// ---------------------------------------------------------------------------
// tf32 GEMM, 3-stage cp.async pipeline, ldmatrix frags, pre-converted inputs.
// C[.,N] tile (row0,col0) = A[M,K]*B[N,K]^T. 128x128 tile, BK=16, 256 thr.
// ---------------------------------------------------------------------------
#define SSTR 20
#define GEMM_STG_WORDS (128 * SSTR)
#define GEMM_SMEM_BYTES (2 * 3 * GEMM_STG_WORDS * 4)   // 61440

__device__ __forceinline__ void gemm_issue(
    unsigned* As, unsigned* Bs,
    const unsigned* A, const unsigned* B, int K, int row0, int col0,
    const int* rr, const int* kk, int kc)
{
#pragma unroll
    for (int it = 0; it < 2; it++) {
        cp16(s2u(&As[rr[it] * SSTR + kk[it]]),
             A + (size_t)(row0 + rr[it]) * K + kc + kk[it]);
        cp16(s2u(&Bs[rr[it] * SSTR + kk[it]]),
             B + (size_t)(col0 + rr[it]) * K + kc + kk[it]);
    }
}

__device__ __forceinline__ void gemm_tile_u(
    const unsigned* __restrict__ A, const unsigned* __restrict__ B,
    float* __restrict__ C, int N, int K, int row0, int col0)
{
    extern __shared__ unsigned gsm[];
    unsigned* Asb = gsm;                        // [3][GEMM_STG_WORDS]
    unsigned* Bsb = gsm + 3 * GEMM_STG_WORDS;

    const int tid  = threadIdx.x;
    const int wid  = tid >> 5;
    const int lane = tid & 31;
    const int g    = lane >> 2;
    const int t    = lane & 3;
    const int wm   = wid & 1;
    const int wn   = wid >> 1;

    const int rowA = (lane & 7) + ((lane >> 3) & 1) * 8;
    const int colA = (lane >> 4) * 4;
    const int rowB = (lane & 7) + (lane >> 4) * 8;
    const int colB = ((lane >> 3) & 1) * 4;

    int rr[2], kk[2];
#pragma unroll
    for (int it = 0; it < 2; it++) {
        int idx = tid + it * 256;
        rr[it] = idx >> 2;
        kk[it] = (idx & 3) * 4;
    }

    gemm_issue(Asb, Bsb, A, B, K, row0, col0, rr, kk, 0);
    CP_COMMIT();
    gemm_issue(Asb + GEMM_STG_WORDS, Bsb + GEMM_STG_WORDS,
               A, B, K, row0, col0, rr, kk, 16);
    CP_COMMIT();

    float c[4][4][4];
#pragma unroll
    for (int mt = 0; mt < 4; mt++)
#pragma unroll
        for (int nt = 0; nt < 4; nt++)
#pragma unroll
            for (int i = 0; i < 4; i++) c[mt][nt][i] = 0.f;

    int s = 0;
    for (int kc = 0; kc < K; kc += 16) {
        CP_WAIT1();
        __syncthreads();

        int kn = kc + 32;
        int sn = s + 2; if (sn >= 3) sn -= 3;
        if (kn < K)
            gemm_issue(Asb + sn * GEMM_STG_WORDS, Bsb + sn * GEMM_STG_WORDS,
                       A, B, K, row0, col0, rr, kk, kn);
        CP_COMMIT();

        unsigned* As = Asb + s * GEMM_STG_WORDS;
        unsigned* Bs = Bsb + s * GEMM_STG_WORDS;
#pragma unroll
        for (int ks = 0; ks < 16; ks += 8) {
            unsigned a[4][4], bf[4][2];
#pragma unroll
            for (int mt = 0; mt < 4; mt++)
                ldsm4(a[mt][0], a[mt][1], a[mt][2], a[mt][3],
                      s2u(&As[(wm * 64 + mt * 16 + rowA) * SSTR + ks + colA]));
#pragma unroll
            for (int p = 0; p < 2; p++) {
                unsigned r0, r1, r2, r3;
                ldsm4(r0, r1, r2, r3,
                      s2u(&Bs[(wn * 32 + p * 16 + rowB) * SSTR + ks + colB]));
                bf[2 * p][0] = r0; bf[2 * p][1] = r1;
                bf[2 * p + 1][0] = r2; bf[2 * p + 1][1] = r3;
            }
#pragma unroll
            for (int mt = 0; mt < 4; mt++)
#pragma unroll
                for (int nt = 0; nt < 4; nt++)
                    mma_tf32(c[mt][nt], a[mt], bf[nt][0], bf[nt][1]);
        }
        s = (s + 1 == 3) ? 0 : s + 1;
        __syncthreads();
    }

#pragma unroll
    for (int mt = 0; mt < 4; mt++) {
#pragma unroll
        for (int nt = 0; nt < 4; nt++) {
            int r  = row0 + wm * 64 + mt * 16 + g;
            int cc = col0 + wn * 32 + nt * 8 + 2 * t;
            float2 lo = make_float2(c[mt][nt][0], c[mt][nt][1]);
            float2 hi = make_float2(c[mt][nt][2], c[mt][nt][3]);
            *(float2*)&C[(size_t)r * N + cc]       = lo;
            *(float2*)&C[(size_t)(r + 8) * N + cc] = hi;
        }
    }
}

__global__ __launch_bounds__(256, 2) void qkv_gemm(
    const unsigned* __restrict__ hidden,
    const unsigned* __restrict__ Wq, const unsigned* __restrict__ Wk,
    const unsigned* __restrict__ Wv,
    float* __restrict__ Qb, float* __restrict__ Kb, float* __restrict__ Vb)
{
    const int bx = blockIdx.x;
    const unsigned* B;
    float* C;
    int Nc, col0;
    if (bx < 16)      { B = Wq; C = Qb; Nc = QC; col0 = bx * 128; }
    else if (bx < 20) { B = Wk; C = Kb; Nc = KC; col0 = (bx - 16) * 128; }
    else              { B = Wv; C = Vb; Nc = KC; col0 = (bx - 20) * 128; }
    gemm_tile_u(hidden, B, C, Nc, Dm, blockIdx.y * 128, col0);
}

__global__ __launch_bounds__(256, 2) void out_gemm(
    const unsigned* __restrict__ A, const unsigned* __restrict__ B,
    float* __restrict__ C)
{
    gemm_tile_u(A, B, C, Dm, Dm, blockIdx.y * 128, blockIdx.x * 128);
}

// ---------------------------------------------------------------------------
// In-place RoPE; writes tf32-rounded bits (idempotent for later consumers)
// ---------------------------------------------------------------------------
__global__ void rope_kernel(float* __restrict__ X,
                            const float* __restrict__ cosb,
                            const float* __restrict__ sinb,
                            int C, int total_pairs)
{
    int idx = blockIdx.x * blockDim.x + threadIdx.x;
    if (idx >= total_pairs) return;
    int per_row = C >> 1;
    int row  = idx / per_row;
    int p    = idx - row * per_row;
    int head = p >> 5;
    int d    = p & 31;
    int col1 = head * 64 + d;
    int col2 = col1 + 32;

    float c1 = cosb[row * 64 + d];
    float s1 = sinb[row * 64 + d];
    float c2 = cosb[row * 64 + d + 32];
    float s2 = sinb[row * 64 + d + 32];

    size_t base = (size_t)row * C;
    float x1 = X[base + col1];
    float x2 = X[base + col2];
    X[base + col1] = __uint_as_float(f2tf32(x1 * c1 - x2 * s1));
    X[base + col2] = __uint_as_float(f2tf32(x2 * c2 + x1 * s2));
}

// ---------------------------------------------------------------------------
// Flash attention v8: tf32, ldmatrix, 256-row q tile, 32 rows/warp,
// double-buffered K/V tiles prefetched with cp.async.
// Smem: Qs[q][d] QTxFST, Ps[q][j] QTxFST, Ks[2][j][d] 64xFST, Vt[2][d][j] 64xFST
// ---------------------------------------------------------------------------
#define QT  256
#define FST 68
#define FLASH_SMEM_WORDS ((2 * QT + 4 * 64) * FST)   // 52224 words = 208896 B

__global__ __launch_bounds__(256, 1) void flash8_kernel(
    const unsigned* __restrict__ Q, const unsigned* __restrict__ K,
    const unsigned* __restrict__ Vt_g, float* __restrict__ O)
{
    const int qt2 = (Sq / QT - 1) - blockIdx.x;   // big blocks first
    const int h   = blockIdx.y;
    const int b   = blockIdx.z;
    const int kvh = h >> 2;

    extern __shared__ unsigned smu[];
    unsigned* Qs  = smu;                          // QT*FST
    unsigned* Ps  = smu + QT * FST;               // QT*FST
    unsigned* Ksb = smu + 2 * QT * FST;           // 2 stages x 64*FST
    unsigned* Vtb = smu + 2 * QT * FST + 2 * 64 * FST;

    const int tid  = threadIdx.x;
    const int w    = tid >> 5;
    const int lane = tid & 31;
    const int g    = lane >> 2;
    const int t    = lane & 3;
    const int q0   = qt2 * QT;
    const int wb   = w * 32;

    const int rowA = (lane & 7) + ((lane >> 3) & 1) * 8;
    const int colA = (lane >> 4) * 4;
    const int rowB = (lane & 7) + (lane >> 4) * 8;
    const int colB = ((lane >> 3) & 1) * 4;

    // per-thread K/V chunk coordinates
    const int lr = tid >> 2;            // row 0..63
    const int cb = (tid & 3) * 16;      // 16-word column base

    const unsigned* Kbase  = K    + (size_t)(b * Sq) * KC + kvh * DH;
    const unsigned* Vtbase = Vt_g + ((size_t)b * KC + kvh * DH + lr) * Sq;

    // Prologue: issue tile kt=0 into stage 0
    {
        const unsigned* kg = Kbase + (size_t)lr * KC + cb;
#pragma unroll
        for (int i = 0; i < 4; i++)
            cp16(s2u(&Ksb[lr * FST + cb + i * 4]), kg + i * 4);
        const unsigned* vg = Vtbase + cb;   // k0 = 0
#pragma unroll
        for (int i = 0; i < 4; i++)
            cp16(s2u(&Vtb[lr * FST + cb + i * 4]), vg + i * 4);
    }
    CP_COMMIT();

    // Load Q tile (QT rows): one row per thread, pre-converted, vectorized
    {
        const unsigned* qg = Q + (size_t)(b * Sq + q0 + tid) * QC + h * DH;
#pragma unroll
        for (int i = 0; i < 16; i++)
            *(uint4*)&Qs[tid * FST + i * 4] = *(const uint4*)(qg + i * 4);
    }

    float m[4], l[4];
#pragma unroll
    for (int i = 0; i < 4; i++) { m[i] = -1e30f; l[i] = 0.f; }
    float acc[2][8][4];
#pragma unroll
    for (int mt = 0; mt < 2; mt++)
#pragma unroll
        for (int nt = 0; nt < 8; nt++)
#pragma unroll
            for (int i = 0; i < 4; i++) acc[mt][nt][i] = 0.f;

    const int wmax  = q0 + wb + 31;
    const int ktmax = (q0 + QT - 1) / 64;

    for (int kt = 0; kt <= ktmax; ++kt) {
        const int k0 = kt * 64;
        const int st = kt & 1;

        __syncthreads();   // all warps done with stage st^1 reads (kt-1)

        // Prefetch tile kt+1 into the other stage
        if (kt < ktmax) {
            const int kn = k0 + 64;
            const unsigned* kg = Kbase + (size_t)(kn + lr) * KC + cb;
            unsigned* Ksn = Ksb + (st ^ 1) * 64 * FST;
            unsigned* Vtn = Vtb + (st ^ 1) * 64 * FST;
#pragma unroll
            for (int i = 0; i < 4; i++)
                cp16(s2u(&Ksn[lr * FST + cb + i * 4]), kg + i * 4);
            const unsigned* vg = Vtbase + kn + cb;
#pragma unroll
            for (int i = 0; i < 4; i++)
                cp16(s2u(&Vtn[lr * FST + cb + i * 4]), vg + i * 4);
        }
        CP_COMMIT();
        CP_WAIT1();        // group for tile kt complete
        __syncthreads();   // visible to all warps

        if (k0 > wmax) continue;   // fully masked for this warp's rows

        unsigned* Ks = Ksb + st * 64 * FST;
        unsigned* Vt = Vtb + st * 64 * FST;

        // ---- S = Q K^T (32x64 per warp) ----
        float sc[2][8][4];
#pragma unroll
        for (int mt = 0; mt < 2; mt++)
#pragma unroll
            for (int nt = 0; nt < 8; nt++)
#pragma unroll
                for (int i = 0; i < 4; i++) sc[mt][nt][i] = 0.f;

#pragma unroll
        for (int ks = 0; ks < 8; ks++) {
            unsigned a[2][4];
#pragma unroll
            for (int mt = 0; mt < 2; mt++)
                ldsm4(a[mt][0], a[mt][1], a[mt][2], a[mt][3],
                      s2u(&Qs[(wb + mt * 16 + rowA) * FST + ks * 8 + colA]));
#pragma unroll
            for (int p = 0; p < 4; p++) {
                unsigned b0, b1, b2, b3;
                ldsm4(b0, b1, b2, b3,
                      s2u(&Ks[(p * 16 + rowB) * FST + ks * 8 + colB]));
#pragma unroll
                for (int mt = 0; mt < 2; mt++) {
                    mma_tf32(sc[mt][2 * p],     a[mt], b0, b1);
                    mma_tf32(sc[mt][2 * p + 1], a[mt], b2, b3);
                }
            }
        }

        // ---- softmax ----
#pragma unroll
        for (int mt = 0; mt < 2; mt++) {
            const int rlo = q0 + wb + mt * 16 + g;
            const int rhi = rlo + 8;
            const bool need_mask = (k0 + 63 > rlo);
            float rmax0 = -1e30f, rmax1 = -1e30f;
#pragma unroll
            for (int nt = 0; nt < 8; nt++) {
#pragma unroll
                for (int c2 = 0; c2 < 2; c2++) {
                    float v0 = sc[mt][nt][c2    ] * 0.125f;
                    float v1 = sc[mt][nt][c2 + 2] * 0.125f;
                    if (need_mask) {
                        int kj = k0 + nt * 8 + 2 * t + c2;
                        if (kj > rlo) v0 = -1e30f;
                        if (kj > rhi) v1 = -1e30f;
                    }
                    sc[mt][nt][c2    ] = v0;
                    sc[mt][nt][c2 + 2] = v1;
                    rmax0 = fmaxf(rmax0, v0);
                    rmax1 = fmaxf(rmax1, v1);
                }
            }
            rmax0 = fmaxf(rmax0, __shfl_xor_sync(0xffffffffu, rmax0, 1));
            rmax0 = fmaxf(rmax0, __shfl_xor_sync(0xffffffffu, rmax0, 2));
            rmax1 = fmaxf(rmax1, __shfl_xor_sync(0xffffffffu, rmax1, 1));
            rmax1 = fmaxf(rmax1, __shfl_xor_sync(0xffffffffu, rmax1, 2));

            float mn0 = fmaxf(m[mt * 2],     rmax0);
            float mn1 = fmaxf(m[mt * 2 + 1], rmax1);
            float corr0 = __expf(m[mt * 2]     - mn0);
            float corr1 = __expf(m[mt * 2 + 1] - mn1);
            m[mt * 2] = mn0; m[mt * 2 + 1] = mn1;

            float ls0 = 0.f, ls1 = 0.f;
#pragma unroll
            for (int nt = 0; nt < 8; nt++) {
#pragma unroll
                for (int c2 = 0; c2 < 2; c2++) {
                    float p0 = __expf(sc[mt][nt][c2    ] - mn0);
                    float p1 = __expf(sc[mt][nt][c2 + 2] - mn1);
                    ls0 += p0; ls1 += p1;
                    int jj = nt * 8 + 2 * t + c2;
                    Ps[(wb + mt * 16 + g    ) * FST + jj] = f2tf32(p0);
                    Ps[(wb + mt * 16 + g + 8) * FST + jj] = f2tf32(p1);
                }
            }
            ls0 += __shfl_xor_sync(0xffffffffu, ls0, 1);
            ls0 += __shfl_xor_sync(0xffffffffu, ls0, 2);
            ls1 += __shfl_xor_sync(0xffffffffu, ls1, 1);
            ls1 += __shfl_xor_sync(0xffffffffu, ls1, 2);
            l[mt * 2]     = l[mt * 2]     * corr0 + ls0;
            l[mt * 2 + 1] = l[mt * 2 + 1] * corr1 + ls1;

#pragma unroll
            for (int nt = 0; nt < 8; nt++) {
                acc[mt][nt][0] *= corr0; acc[mt][nt][1] *= corr0;
                acc[mt][nt][2] *= corr1; acc[mt][nt][3] *= corr1;
            }
        }

        __syncwarp();   // Ps rows warp-local: order STS before ldmatrix

        // ---- acc += P V ----
#pragma unroll
        for (int ks = 0; ks < 8; ks++) {
            unsigned a[2][4];
#pragma unroll
            for (int mt = 0; mt < 2; mt++)
                ldsm4(a[mt][0], a[mt][1], a[mt][2], a[mt][3],
                      s2u(&Ps[(wb + mt * 16 + rowA) * FST + ks * 8 + colA]));
#pragma unroll
            for (int p = 0; p < 4; p++) {
                unsigned b0, b1, b2, b3;
                ldsm4(b0, b1, b2, b3,
                      s2u(&Vt[(p * 16 + rowB) * FST + ks * 8 + colB]));
#pragma unroll
                for (int mt = 0; mt < 2; mt++) {
                    mma_tf32(acc[mt][2 * p],     a[mt], b0, b1);
                    mma_tf32(acc[mt][2 * p + 1], a[mt], b2, b3);
                }
            }
        }
    }

    // Epilogue (tf32-rounded for the out-projection's A operand)
#pragma unroll
    for (int mt = 0; mt < 2; mt++) {
        float inv0 = 1.f / l[mt * 2];
        float inv1 = 1.f / l[mt * 2 + 1];
        size_t orow0 = (size_t)(b * Sq + q0 + wb + mt * 16 + g) * QC;
        size_t orow1 = orow0 + 8 * (size_t)QC;
#pragma unroll
        for (int nt = 0; nt < 8; nt++) {
            int col = h * DH + nt * 8 + 2 * t;
            float2 lo = make_float2(
                __uint_as_float(f2tf32(acc[mt][nt][0] * inv0)),
                __uint_as_float(f2tf32(acc[mt][nt][1] * inv0)));
            float2 hi = make_float2(
                __uint_as_float(f2tf32(acc[mt][nt][2] * inv1)),
                __uint_as_float(f2tf32(acc[mt][nt][3] * inv1)));
            *(float2*)&O[orow0 + col] = lo;
            *(float2*)&O[orow1 + col] = hi;
        }
    }
}

// ---------------------------------------------------------------------------
// kernel_launch
// ---------------------------------------------------------------------------
extern "C" void kernel_launch(void* const* d_in, const int* in_sizes, int n_in,
                              void* d_out, int out_size)
{
    const float* hidden = (const float*)d_in[0];
    const float* cosb   = (const float*)d_in[1];
    const float* sinb   = (const float*)d_in[2];
    const float* Wq     = (const float*)d_in[4];
    const float* Wk     = (const float*)d_in[5];
    const float* Wv     = (const float*)d_in[6];
    const float* Wo     = (const float*)d_in[7];
    float* out = (float*)d_out;

    float *Qb, *Kb, *Vb, *Ob;
    unsigned *h32, *wq32, *wk32, *wv32, *wo32, *vt32;
    cudaGetSymbolAddress((void**)&Qb, g_Q);
    cudaGetSymbolAddress((void**)&Kb, g_K);
    cudaGetSymbolAddress((void**)&Vb, g_V);
    cudaGetSymbolAddress((void**)&Ob, g_O);
    cudaGetSymbolAddress((void**)&h32,  g_h32);
    cudaGetSymbolAddress((void**)&wq32, g_wq32);
    cudaGetSymbolAddress((void**)&wk32, g_wk32);
    cudaGetSymbolAddress((void**)&wv32, g_wv32);
    cudaGetSymbolAddress((void**)&wo32, g_wo32);
    cudaGetSymbolAddress((void**)&vt32, g_Vt32);

    // Pre-convert inputs to tf32 bit patterns
    {
        struct { const float* s; unsigned* d; size_t n; } jobs[5] = {
            { hidden, h32,  (size_t)ROWS * Dm },
            { Wq,     wq32, (size_t)QC * Dm },
            { Wk,     wk32, (size_t)KC * Dm },
            { Wv,     wv32, (size_t)KC * Dm },
            { Wo,     wo32, (size_t)Dm * Dm },
        };
        for (int j = 0; j < 5; j++) {
            int n4 = (int)(jobs[j].n / 4);
            cvt_tf32_kernel<<<(n4 + 255) / 256, 256>>>(
                (const float4*)jobs[j].s, (uint4*)jobs[j].d, n4);
        }
    }

    // Fused QKV projections (cp.async pipeline)
    cudaFuncSetAttribute(qkv_gemm,
        cudaFuncAttributeMaxDynamicSharedMemorySize, GEMM_SMEM_BYTES);
    qkv_gemm<<<dim3(24, ROWS / 128), 256, GEMM_SMEM_BYTES>>>(
        h32, wq32, wk32, wv32, Qb, Kb, Vb);

    // RoPE on Q and K (writes tf32-rounded)
    {
        int pq = ROWS * (QC / 2);
        rope_kernel<<<(pq + 255) / 256, 256>>>(Qb, cosb, sinb, QC, pq);
        int pk = ROWS * (KC / 2);
        rope_kernel<<<(pk + 255) / 256, 256>>>(Kb, cosb, sinb, KC, pk);
    }

    // Transpose V to [KC][Sq], tf32
    transpose_v_kernel<<<dim3(Sq / 32, KC / 32, Bsz), dim3(32, 8)>>>(Vb, vt32);

    // Flash attention (tf32, double-buffered cp.async K/V)
    {
        int smem_bytes = FLASH_SMEM_WORDS * (int)sizeof(unsigned);  // 208896
        cudaFuncSetAttribute(flash8_kernel,
            cudaFuncAttributeMaxDynamicSharedMemorySize, smem_bytes);
        dim3 grid(Sq / QT, Hh, Bsz);
        flash8_kernel<<<grid, 256, smem_bytes>>>(
            (const unsigned*)Qb, (const unsigned*)Kb, vt32, Ob);
    }

    // Output projection
    cudaFuncSetAttribute(out_gemm,
        cudaFuncAttributeMaxDynamicSharedMemorySize, GEMM_SMEM_BYTES);
    out_gemm<<<dim3(Dm / 128, ROWS / 128), 256, GEMM_SMEM_BYTES>>>(
        (const unsigned*)Ob, wo32, out);
}